// round 11
// baseline (speedup 1.0000x reference)
#include <cuda_runtime.h>
#include <cuda_bf16.h>
#include <cstdint>

#define BSZ      2
#define SEQ      2048
#define DIM      2048
#define N_HEADS  32
#define N_KVH    8
#define HD       64
#define ROWS     (BSZ*SEQ)          // 4096
#define KVDIM    (N_KVH*HD)         // 512
#define KP       (DIM/2)            // 1024 u32 pairs per DIM row
#define KVP      (KVDIM/2)          // 256
#define NW       (DIM + 2*KVDIM)    // 3072 fused qkv width

// ---------------- scratch (device globals; no allocations allowed) ----------
__device__ __align__(256) float    g_V[ROWS * KVDIM];
__device__ __align__(256) uint32_t g_xh [ROWS * KP],  g_xl [ROWS * KP];
__device__ __align__(256) uint32_t g_wTh[NW * KP],    g_wTl[NW * KP];    // wqT||wkT||wvT
__device__ __align__(256) uint32_t g_woTh[DIM * KP],  g_woTl[DIM * KP];
__device__ __align__(256) uint32_t g_Qh[ROWS * KP],   g_Ql[ROWS * KP];
__device__ __align__(256) uint32_t g_Kh[ROWS * KVP],  g_Kl[ROWS * KVP];  // K full split (restored)
__device__ __align__(256) uint32_t g_Vth[BSZ*N_KVH*HD*(SEQ/2)], g_Vtl[BSZ*N_KVH*HD*(SEQ/2)];
__device__ __align__(256) uint32_t g_Ah[ROWS * KP],   g_Al[ROWS * KP];

// ---------------- helpers ----------------------------------------------------
__device__ __forceinline__ void split_pack(float x, float y, uint32_t& hv, uint32_t& lv) {
    __nv_bfloat162 hb = __floats2bfloat162_rn(x, y);
    hv = *reinterpret_cast<uint32_t*>(&hb);
    float rx = x - __bfloat162float(hb.x);
    float ry = y - __bfloat162float(hb.y);
    __nv_bfloat162 lb = __floats2bfloat162_rn(rx, ry);
    lv = *reinterpret_cast<uint32_t*>(&lb);
}

__device__ __forceinline__ void mma_bf16(float* c,
        uint32_t a0, uint32_t a1, uint32_t a2, uint32_t a3,
        uint32_t b0, uint32_t b1) {
    asm volatile(
        "mma.sync.aligned.m16n8k16.row.col.f32.bf16.bf16.f32 "
        "{%0,%1,%2,%3}, {%4,%5,%6,%7}, {%8,%9}, {%0,%1,%2,%3};"
        : "+f"(c[0]), "+f"(c[1]), "+f"(c[2]), "+f"(c[3])
        : "r"(a0), "r"(a1), "r"(a2), "r"(a3), "r"(b0), "r"(b1));
}

__device__ __forceinline__ void ldm4(uint32_t* r, uint32_t addr) {
    asm volatile("ldmatrix.sync.aligned.m8n8.x4.shared.b16 {%0,%1,%2,%3}, [%4];"
                 : "=r"(r[0]), "=r"(r[1]), "=r"(r[2]), "=r"(r[3]) : "r"(addr));
}

__device__ __forceinline__ float ex2(float x) {
    float y;
    asm("ex2.approx.ftz.f32 %0, %1;" : "=f"(y) : "f"(x));
    return y;
}

__device__ __forceinline__ void cpa16(uint32_t dst_smem, const void* src) {
    asm volatile("cp.async.cg.shared.global [%0], [%1], 16;\n"
                 :: "r"(dst_smem), "l"(src));
}
#define CP_COMMIT asm volatile("cp.async.commit_group;\n" ::)
#define CP_WAIT0  asm volatile("cp.async.wait_group 0;\n" ::)
#define CP_WAIT1  asm volatile("cp.async.wait_group 1;\n" ::)

// rope + split store of a (even,odd) column pair (hi+lo)
__device__ __forceinline__ void rope_split_store(
        uint32_t* __restrict__ dh, uint32_t* __restrict__ dl, int ldp,
        int row, int col, float2 v,
        const float* __restrict__ cs, const float* __restrict__ sn) {
    int s = row & (SEQ - 1);
    int p = (col & 63) >> 1;
    float c = cs[s * 32 + p], si = sn[s * 32 + p];
    float orr = v.x * c - v.y * si;
    float oi  = v.x * si + v.y * c;
    uint32_t h, l;
    split_pack(orr, oi, h, l);
    size_t o = (size_t)row * ldp + (col >> 1);
    dh[o] = h; dl[o] = l;
}

// ---------------- conversion kernels ----------------------------------------
__global__ void conv_x(const float* __restrict__ x,
                       uint32_t* __restrict__ xh, uint32_t* __restrict__ xl,
                       int npairs) {
    int i = blockIdx.x * blockDim.x + threadIdx.x;
    if (i >= npairs) return;
    float2 v = *(const float2*)(x + 2 * (size_t)i);
    uint32_t h, l;
    split_pack(v.x, v.y, h, l);
    xh[i] = h; xl[i] = l;
}

__global__ __launch_bounds__(256) void tconv_all(
        const float* __restrict__ wq, const float* __restrict__ wk,
        const float* __restrict__ wv, const float* __restrict__ wo,
        uint32_t* __restrict__ Th, uint32_t* __restrict__ Tl,
        uint32_t* __restrict__ Oh, uint32_t* __restrict__ Ol) {
    __shared__ float s[64][33];
    const int tid = threadIdx.x;
    const int bx = blockIdx.x, k0 = blockIdx.y * 64;
    const float* W; int N, rowoff, nb;
    uint32_t *Dh, *Dl;
    if (bx < 64)       { W = wq; N = DIM;   rowoff = 0;           nb = bx;      Dh = Th; Dl = Tl; }
    else if (bx < 80)  { W = wk; N = KVDIM; rowoff = DIM;         nb = bx - 64; Dh = Th; Dl = Tl; }
    else if (bx < 96)  { W = wv; N = KVDIM; rowoff = DIM + KVDIM; nb = bx - 80; Dh = Th; Dl = Tl; }
    else               { W = wo; N = DIM;   rowoff = 0;           nb = bx - 96; Dh = Oh; Dl = Ol; }
    const int n0 = nb * 32;
    #pragma unroll
    for (int jj = 0; jj < 8; jj++) {
        int id = tid + 256 * jj;
        int k = id >> 5, n = id & 31;
        s[k][n] = W[(size_t)(k0 + k) * N + n0 + n];
    }
    __syncthreads();
    #pragma unroll
    for (int jj = 0; jj < 4; jj++) {
        int id = tid + 256 * jj;
        int n = id >> 5, kp = id & 31;
        uint32_t h, l;
        split_pack(s[2 * kp][n], s[2 * kp + 1][n], h, l);
        size_t o = (size_t)(rowoff + n0 + n) * KP + (k0 >> 1) + kp;
        Dh[o] = h; Dl[o] = l;
    }
}

__global__ __launch_bounds__(256) void vt_conv(const float* __restrict__ V,
                                               uint32_t* __restrict__ Vth,
                                               uint32_t* __restrict__ Vtl) {
    __shared__ float s[32][65];
    const int tid = threadIdx.x;
    const int s0 = blockIdx.x * 32;
    const int bz = blockIdx.z;
    const int b = bz >> 3, kvh = bz & 7;
    #pragma unroll
    for (int jj = 0; jj < 8; jj++) {
        int id = tid + 256 * jj;
        int si = id >> 6, d = id & 63;
        s[si][d] = V[(size_t)(b * SEQ + s0 + si) * KVDIM + kvh * HD + d];
    }
    __syncthreads();
    #pragma unroll
    for (int jj = 0; jj < 4; jj++) {
        int id = tid + 256 * jj;
        int d = id >> 4, sp = id & 15;
        uint32_t h, l;
        split_pack(s[2 * sp][d], s[2 * sp + 1][d], h, l);
        size_t o = (size_t)(bz * HD + d) * (SEQ / 2) + (s0 >> 1) + sp;
        Vth[o] = h; Vtl[o] = l;
    }
}

// ---------------- split-bf16 GEMM (ldmatrix + 2-stage cp.async) -------------
#define SG        20
#define TBUF_U32  (4 * 128 * SG)
#define TBUF_B    (TBUF_U32 * 4)
#define AREA_AL   (128 * SG * 4)
#define AREA_BH   (2 * 128 * SG * 4)
#define AREA_BL   (3 * 128 * SG * 4)

template <bool QKV>
__global__ __launch_bounds__(256) void gemm_bf16(
        const uint32_t* __restrict__ Ah, const uint32_t* __restrict__ Al,
        const uint32_t* __restrict__ Bh, const uint32_t* __restrict__ Bl,
        float* __restrict__ Cout,
        const float* __restrict__ cs, const float* __restrict__ sn, int K) {
    extern __shared__ uint32_t sm[];
    const int KPL = K >> 1;
    const int tid = threadIdx.x;
    const int warp = tid >> 5, lane = tid & 31;
    const int tg = lane >> 2, t4 = lane & 3;
    const int wm = (warp >> 2) * 64;
    const int wn = (warp & 3) * 32;
    const int bx = blockIdx.x, by = blockIdx.y;

    const int mrow = ((lane >> 3) & 1) * 8 + (lane & 7);
    const int mcol = (lane >> 4) * 4;
    int aoff[4], boff[2];
    #pragma unroll
    for (int i = 0; i < 4; i++) aoff[i] = (wm + 16 * i + mrow) * SG + mcol;
    #pragma unroll
    for (int jj = 0; jj < 2; jj++) boff[jj] = (wn + 16 * jj + mrow) * SG + mcol;

    const uint32_t* src[8];
    uint32_t dstoff[8];
    #pragma unroll
    for (int jj = 0; jj < 8; jj++) {
        int id = tid + 256 * jj;
        int arr = id >> 9, rem = id & 511;
        int row = rem >> 2, ch = rem & 3;
        const uint32_t* base =
            (arr == 0) ? Ah + (size_t)(by * 128 + row) * KPL :
            (arr == 1) ? Al + (size_t)(by * 128 + row) * KPL :
            (arr == 2) ? Bh + (size_t)(bx * 128 + row) * KPL :
                         Bl + (size_t)(bx * 128 + row) * KPL;
        src[jj] = base + ch * 4;
        dstoff[jj] = arr * (128 * SG) + row * SG + ch * 4;
    }
    uint32_t sbase = (uint32_t)__cvta_generic_to_shared(sm);

    float acc[4][4][4];
    #pragma unroll
    for (int i = 0; i < 4; i++)
        #pragma unroll
        for (int j = 0; j < 4; j++)
            #pragma unroll
            for (int c = 0; c < 4; c++) acc[i][j][c] = 0.f;

    const int nk = K >> 5;

    #pragma unroll
    for (int jj = 0; jj < 8; jj++)
        cpa16(sbase + dstoff[jj] * 4, src[jj]);
    CP_COMMIT;

    for (int kc = 0; kc < nk; kc++) {
        int cur = kc & 1;
        if (kc + 1 < nk) {
            uint32_t bb = sbase + (cur ^ 1) * TBUF_B;
            int kadv = (kc + 1) * 16;
            #pragma unroll
            for (int jj = 0; jj < 8; jj++)
                cpa16(bb + dstoff[jj] * 4, src[jj] + kadv);
            CP_COMMIT;
            CP_WAIT1;
        } else {
            CP_WAIT0;
        }
        __syncthreads();

        uint32_t bb = sbase + cur * TBUF_B;
        #pragma unroll
        for (int s = 0; s < 2; s++) {
            uint32_t aH[4][4], aL[4][4];
            #pragma unroll
            for (int i = 0; i < 4; i++) {
                ldm4(aH[i], bb + (aoff[i] + 8 * s) * 4);
                ldm4(aL[i], bb + AREA_AL + (aoff[i] + 8 * s) * 4);
            }
            #pragma unroll
            for (int jj = 0; jj < 2; jj++) {
                uint32_t bh[4], bl[4];
                ldm4(bh, bb + AREA_BH + (boff[jj] + 8 * s) * 4);
                ldm4(bl, bb + AREA_BL + (boff[jj] + 8 * s) * 4);
                #pragma unroll
                for (int i = 0; i < 4; i++) {
                    float* c0 = acc[i][2 * jj];
                    float* c1 = acc[i][2 * jj + 1];
                    mma_bf16(c0, aH[i][0], aH[i][1], aH[i][2], aH[i][3], bh[0], bh[2]);
                    mma_bf16(c0, aH[i][0], aH[i][1], aH[i][2], aH[i][3], bl[0], bl[2]);
                    mma_bf16(c0, aL[i][0], aL[i][1], aL[i][2], aL[i][3], bh[0], bh[2]);
                    mma_bf16(c1, aH[i][0], aH[i][1], aH[i][2], aH[i][3], bh[1], bh[3]);
                    mma_bf16(c1, aH[i][0], aH[i][1], aH[i][2], aH[i][3], bl[1], bl[3]);
                    mma_bf16(c1, aL[i][0], aL[i][1], aL[i][2], aL[i][3], bh[1], bh[3]);
                }
            }
        }
        __syncthreads();
    }

    // ---- epilogue ----
    #pragma unroll
    for (int i = 0; i < 4; i++) {
        int r0 = by * 128 + wm + 16 * i + tg;
        #pragma unroll
        for (int j = 0; j < 4; j++) {
            int col = bx * 128 + wn + 8 * j + 2 * t4;
            float2 v0 = make_float2(acc[i][j][0], acc[i][j][1]);
            float2 v1 = make_float2(acc[i][j][2], acc[i][j][3]);
            if (QKV) {
                if (col < DIM) {
                    rope_split_store(g_Qh, g_Ql, KP, r0, col, v0, cs, sn);
                    rope_split_store(g_Qh, g_Ql, KP, r0 + 8, col, v1, cs, sn);
                } else if (col < DIM + KVDIM) {
                    int c2 = col - DIM;
                    rope_split_store(g_Kh, g_Kl, KVP, r0, c2, v0, cs, sn);
                    rope_split_store(g_Kh, g_Kl, KVP, r0 + 8, c2, v1, cs, sn);
                } else {
                    int c2 = col - DIM - KVDIM;
                    *(float2*)(g_V + (size_t)r0 * KVDIM + c2) = v0;
                    *(float2*)(g_V + (size_t)(r0 + 8) * KVDIM + c2) = v1;
                }
            } else {
                *(float2*)(Cout + (size_t)r0 * DIM + col) = v0;
                *(float2*)(Cout + (size_t)(r0 + 8) * DIM + col) = v1;
            }
        }
    }
}

// ---------------- causal flash attention ------------------------------------
// Full 3-term S and PV (accuracy-proven), register-direct P fragments,
// exp2/FFMA softmax, warp-skip, heavy-first scheduling, deferred l-reduction.
// smem = 73,728 B.
#define SAT   36
#define KVBUF (4 * 64 * SAT)

__global__ __launch_bounds__(256) void attn_mma() {
    extern __shared__ uint32_t smu[];

    const int qt = (int)gridDim.x - 1 - (int)blockIdx.x;   // heavy tiles first
    const int h = blockIdx.y, b = blockIdx.z;
    const int kvh = h >> 2;
    const int tid = threadIdx.x;
    const int w = tid >> 5, lane = tid & 31;
    const int tg = lane >> 2, t4 = lane & 3;
    const int rA = w * 16 + tg, rB = rA + 8;
    const int rowAg = b * SEQ + qt * 128 + rA;
    const int rowBg = rowAg + 8;
    const int wrowmax = qt * 128 + w * 16 + 15;

    const int mrow = ((lane >> 3) & 1) * 8 + (lane & 7);
    const int mcol = (lane >> 4) * 4;
    int nfoff[4];
    #pragma unroll
    for (int jj = 0; jj < 4; jj++) nfoff[jj] = (16 * jj + mrow) * SAT + mcol;

    // cp.async slots: 4 arrays (KH, KL, VH, VL) -> 8 slots/thread
    const uint32_t* src[8];
    int step[8];
    uint32_t dstoff[8];
    #pragma unroll
    for (int jj = 0; jj < 8; jj++) {
        int id = tid + 256 * jj;
        int arr = id >> 9, rem = id & 511;
        int row = rem >> 3, ch = rem & 7;
        const uint32_t* base;
        if (arr == 0)      base = g_Kh + (size_t)(b * SEQ + row) * KVP + kvh * 32;
        else if (arr == 1) base = g_Kl + (size_t)(b * SEQ + row) * KVP + kvh * 32;
        else if (arr == 2) base = g_Vth + (size_t)((b * 8 + kvh) * HD + row) * (SEQ / 2);
        else               base = g_Vtl + (size_t)((b * 8 + kvh) * HD + row) * (SEQ / 2);
        src[jj] = base + ch * 4;
        step[jj] = (arr < 2) ? 64 * KVP : 32;
        dstoff[jj] = arr * (64 * SAT) + row * SAT + ch * 4;
    }
    uint32_t sbase = (uint32_t)__cvta_generic_to_shared(smu);

    uint32_t qH[4][4], qL[4][4];
    {
        const uint32_t* QA = g_Qh + (size_t)rowAg * KP + h * 32;
        const uint32_t* QB = g_Qh + (size_t)rowBg * KP + h * 32;
        const uint32_t* qA = g_Ql + (size_t)rowAg * KP + h * 32;
        const uint32_t* qB = g_Ql + (size_t)rowBg * KP + h * 32;
        #pragma unroll
        for (int s = 0; s < 4; s++) {
            qH[s][0] = QA[8 * s + t4];     qH[s][1] = QB[8 * s + t4];
            qH[s][2] = QA[8 * s + t4 + 4]; qH[s][3] = QB[8 * s + t4 + 4];
            qL[s][0] = qA[8 * s + t4];     qL[s][1] = qB[8 * s + t4];
            qL[s][2] = qA[8 * s + t4 + 4]; qL[s][3] = qB[8 * s + t4 + 4];
        }
    }

    float oacc[8][4];
    #pragma unroll
    for (int j = 0; j < 8; j++)
        #pragma unroll
        for (int c = 0; c < 4; c++) oacc[j][c] = 0.f;
    float mA = -1e30f, mB = -1e30f, lA = 0.f, lB = 0.f;   // l = per-thread partial
    const float SCL = 0.18033688011112042f;   // 0.125 * log2(e)

    const int nkb = 2 * qt + 2;

    #pragma unroll
    for (int jj = 0; jj < 8; jj++)
        cpa16(sbase + dstoff[jj] * 4, src[jj]);
    CP_COMMIT;

    for (int kb = 0; kb < nkb; kb++) {
        int cur = kb & 1;
        if (kb + 1 < nkb) {
            uint32_t boff = sbase + (cur ^ 1) * (KVBUF * 4);
            #pragma unroll
            for (int jj = 0; jj < 8; jj++)
                cpa16(boff + dstoff[jj] * 4, src[jj] + (size_t)(kb + 1) * step[jj]);
            CP_COMMIT;
            CP_WAIT1;
        } else {
            CP_WAIT0;
        }
        __syncthreads();

        if (kb * 64 <= wrowmax) {
            uint32_t kvb = sbase + cur * (KVBUF * 4);
            const uint32_t KLo = 64 * SAT * 4;
            const uint32_t VHo = 2 * 64 * SAT * 4;
            const uint32_t VLo = 3 * 64 * SAT * 4;

            // ---- S = Q K^T (full 3-term) ----
            float sacc[8][4];
            #pragma unroll
            for (int j = 0; j < 8; j++)
                #pragma unroll
                for (int c = 0; c < 4; c++) sacc[j][c] = 0.f;
            #pragma unroll
            for (int s = 0; s < 4; s++) {
                #pragma unroll
                for (int jj = 0; jj < 4; jj++) {
                    uint32_t kh[4], kl[4];
                    ldm4(kh, kvb + (nfoff[jj] + 8 * s) * 4);
                    ldm4(kl, kvb + KLo + (nfoff[jj] + 8 * s) * 4);
                    float* c0 = sacc[2 * jj];
                    float* c1 = sacc[2 * jj + 1];
                    mma_bf16(c0, qH[s][0], qH[s][1], qH[s][2], qH[s][3], kh[0], kh[2]);
                    mma_bf16(c0, qH[s][0], qH[s][1], qH[s][2], qH[s][3], kl[0], kl[2]);
                    mma_bf16(c0, qL[s][0], qL[s][1], qL[s][2], qL[s][3], kh[0], kh[2]);
                    mma_bf16(c1, qH[s][0], qH[s][1], qH[s][2], qH[s][3], kh[1], kh[3]);
                    mma_bf16(c1, qH[s][0], qH[s][1], qH[s][2], qH[s][3], kl[1], kl[3]);
                    mma_bf16(c1, qL[s][0], qL[s][1], qL[s][2], qL[s][3], kh[1], kh[3]);
                }
            }
            // causal mask on raw scores (diagonal tiles)
            if (kb >= 2 * qt) {
                int rGA = qt * 128 + rA, rGB = rGA + 8;
                #pragma unroll
                for (int j = 0; j < 8; j++) {
                    int c0 = kb * 64 + 8 * j + 2 * t4;
                    if (c0 > rGA)     sacc[j][0] = -1e30f;
                    if (c0 + 1 > rGA) sacc[j][1] = -1e30f;
                    if (c0 > rGB)     sacc[j][2] = -1e30f;
                    if (c0 + 1 > rGB) sacc[j][3] = -1e30f;
                }
            }

            // ---- online softmax: max on raw, exp via FFMA + ex2 ----
            float mxA = -1e30f, mxB = -1e30f;
            #pragma unroll
            for (int j = 0; j < 8; j++) {
                mxA = fmaxf(mxA, fmaxf(sacc[j][0], sacc[j][1]));
                mxB = fmaxf(mxB, fmaxf(sacc[j][2], sacc[j][3]));
            }
            mxA = fmaxf(mxA, __shfl_xor_sync(0xffffffffu, mxA, 1));
            mxA = fmaxf(mxA, __shfl_xor_sync(0xffffffffu, mxA, 2));
            mxB = fmaxf(mxB, __shfl_xor_sync(0xffffffffu, mxB, 1));
            mxB = fmaxf(mxB, __shfl_xor_sync(0xffffffffu, mxB, 2));
            float nmA = fmaxf(mA, mxA * SCL), nmB = fmaxf(mB, mxB * SCL);
            float aA = ex2(mA - nmA), aB = ex2(mB - nmB);
            mA = nmA; mB = nmB;
            float sumA = 0.f, sumB = 0.f;
            uint32_t ph01[8], ph23[8], pl01[8], pl23[8];
            #pragma unroll
            for (int j = 0; j < 8; j++) {
                float p0 = ex2(fmaf(sacc[j][0], SCL, -nmA));
                float p1 = ex2(fmaf(sacc[j][1], SCL, -nmA));
                float p2 = ex2(fmaf(sacc[j][2], SCL, -nmB));
                float p3 = ex2(fmaf(sacc[j][3], SCL, -nmB));
                sumA += p0 + p1; sumB += p2 + p3;
                split_pack(p0, p1, ph01[j], pl01[j]);
                split_pack(p2, p3, ph23[j], pl23[j]);
            }
            // deferred l: per-thread partial only (alpha is row-uniform)
            lA = lA * aA + sumA;
            lB = lB * aB + sumB;
            #pragma unroll
            for (int j = 0; j < 8; j++) {
                oacc[j][0] *= aA; oacc[j][1] *= aA;
                oacc[j][2] *= aB; oacc[j][3] *= aB;
            }

            // ---- O += P @ V (full 3-term) ----
            #pragma unroll
            for (int s = 0; s < 4; s++) {
                uint32_t aH0 = ph01[2 * s],     aH1 = ph23[2 * s];
                uint32_t aH2 = ph01[2 * s + 1], aH3 = ph23[2 * s + 1];
                uint32_t aL0 = pl01[2 * s],     aL1 = pl23[2 * s];
                uint32_t aL2 = pl01[2 * s + 1], aL3 = pl23[2 * s + 1];
                #pragma unroll
                for (int jj = 0; jj < 4; jj++) {
                    uint32_t vh[4], vl[4];
                    ldm4(vh, kvb + VHo + (nfoff[jj] + 8 * s) * 4);
                    ldm4(vl, kvb + VLo + (nfoff[jj] + 8 * s) * 4);
                    float* c0 = oacc[2 * jj];
                    float* c1 = oacc[2 * jj + 1];
                    mma_bf16(c0, aH0, aH1, aH2, aH3, vh[0], vh[2]);
                    mma_bf16(c0, aH0, aH1, aH2, aH3, vl[0], vl[2]);
                    mma_bf16(c0, aL0, aL1, aL2, aL3, vh[0], vh[2]);
                    mma_bf16(c1, aH0, aH1, aH2, aH3, vh[1], vh[3]);
                    mma_bf16(c1, aH0, aH1, aH2, aH3, vl[1], vl[3]);
                    mma_bf16(c1, aL0, aL1, aL2, aL3, vh[1], vh[3]);
                }
            }
        }
        __syncthreads();
    }

    // final cross-thread l reduction (deferred from the mainloop)
    lA += __shfl_xor_sync(0xffffffffu, lA, 1);
    lA += __shfl_xor_sync(0xffffffffu, lA, 2);
    lB += __shfl_xor_sync(0xffffffffu, lB, 1);
    lB += __shfl_xor_sync(0xffffffffu, lB, 2);

    float ilA = 1.f / lA, ilB = 1.f / lB;
    #pragma unroll
    for (int j = 0; j < 8; j++) {
        uint32_t hh, ll;
        size_t oA = (size_t)rowAg * KP + h * 32 + 4 * j + t4;
        size_t oB = (size_t)rowBg * KP + h * 32 + 4 * j + t4;
        split_pack(oacc[j][0] * ilA, oacc[j][1] * ilA, hh, ll);
        g_Ah[oA] = hh; g_Al[oA] = ll;
        split_pack(oacc[j][2] * ilB, oacc[j][3] * ilB, hh, ll);
        g_Ah[oB] = hh; g_Al[oB] = ll;
    }
}

// ---------------- launch ----------------------------------------------------
extern "C" void kernel_launch(void* const* d_in, const int* in_sizes, int n_in,
                              void* d_out, int out_size) {
    const float* x  = (const float*)d_in[0];
    const float* fc = (const float*)d_in[1];
    const float* fs = (const float*)d_in[2];
    const float* wq = (const float*)d_in[3];
    const float* wk = (const float*)d_in[4];
    const float* wv = (const float*)d_in[5];
    const float* wo = (const float*)d_in[6];
    float* out = (float*)d_out;

    void *pV, *pxh, *pxl, *pwh, *pwl, *pwoh, *pwol;
    void *pVth, *pVtl, *pAh, *pAl;
    cudaGetSymbolAddress(&pV, g_V);
    cudaGetSymbolAddress(&pxh, g_xh);   cudaGetSymbolAddress(&pxl, g_xl);
    cudaGetSymbolAddress(&pwh, g_wTh);  cudaGetSymbolAddress(&pwl, g_wTl);
    cudaGetSymbolAddress(&pwoh, g_woTh); cudaGetSymbolAddress(&pwol, g_woTl);
    cudaGetSymbolAddress(&pVth, g_Vth); cudaGetSymbolAddress(&pVtl, g_Vtl);
    cudaGetSymbolAddress(&pAh, g_Ah);   cudaGetSymbolAddress(&pAl, g_Al);

    // ---- one-shot conversions ----
    conv_x<<<(ROWS * KP + 255) / 256, 256>>>(x, (uint32_t*)pxh, (uint32_t*)pxl, ROWS * KP);
    tconv_all<<<dim3(160, DIM / 64), 256>>>(wq, wk, wv, wo,
        (uint32_t*)pwh, (uint32_t*)pwl, (uint32_t*)pwoh, (uint32_t*)pwol);

    size_t gsmem = 2 * TBUF_B;   // 81920 B -> 2 CTAs/SM
    cudaFuncSetAttribute(gemm_bf16<true>,  cudaFuncAttributeMaxDynamicSharedMemorySize, (int)gsmem);
    cudaFuncSetAttribute(gemm_bf16<false>, cudaFuncAttributeMaxDynamicSharedMemorySize, (int)gsmem);

    // ---- fused QKV projection (epilogue applies rope + split) ----
    gemm_bf16<true><<<dim3(NW / 128, ROWS / 128), 256, gsmem>>>(
        (uint32_t*)pxh, (uint32_t*)pxl, (uint32_t*)pwh, (uint32_t*)pwl,
        nullptr, fc, fs, DIM);

    // ---- V transpose-split ----
    vt_conv<<<dim3(SEQ / 32, 1, BSZ * N_KVH), 256>>>((float*)pV,
                                                     (uint32_t*)pVth, (uint32_t*)pVtl);

    // ---- attention ----
    {
        size_t smem = 2 * KVBUF * sizeof(uint32_t);  // 73728 B
        cudaFuncSetAttribute(attn_mma, cudaFuncAttributeMaxDynamicSharedMemorySize, (int)smem);
        attn_mma<<<dim3(SEQ / 128, N_HEADS, BSZ), 256, smem>>>();
    }

    // ---- output projection ----
    gemm_bf16<false><<<dim3(DIM / 128, ROWS / 128), 256, gsmem>>>(
        (uint32_t*)pAh, (uint32_t*)pAl, (uint32_t*)pwoh, (uint32_t*)pwol,
        out, nullptr, nullptr, DIM);
}

// round 12
// speedup vs baseline: 1.3901x; 1.3901x over previous
#include <cuda_runtime.h>
#include <cuda_fp16.h>
#include <cstdint>

#define BSZ      2
#define SEQ      2048
#define DIM      2048
#define N_HEADS  32
#define N_KVH    8
#define HD       64
#define ROWS     (BSZ*SEQ)          // 4096
#define KVDIM    (N_KVH*HD)         // 512
#define KP       (DIM/2)            // 1024 u32 pairs per DIM row
#define KVP      (KVDIM/2)          // 256
#define NW       (DIM + 2*KVDIM)    // 3072 fused qkv width

// ---------------- scratch (device globals; no allocations allowed) ----------
__device__ __align__(256) float    g_V[ROWS * KVDIM];
__device__ __align__(256) uint32_t g_xh [ROWS * KP],  g_xl [ROWS * KP];   // x fp16 hi/lo
__device__ __align__(256) uint32_t g_wTh[NW * KP];                        // W^T fp16 hi (x64)
__device__ __align__(256) uint32_t g_woTh[DIM * KP];                      // Wo^T fp16 hi (x64)
__device__ __align__(256) uint32_t g_Qh[ROWS * KP],   g_Ql[ROWS * KP];    // Q fp16 hi/lo (roped)
__device__ __align__(256) uint32_t g_Kh[ROWS * KVP];                      // K fp16 hi (roped)
__device__ __align__(256) uint32_t g_Vth[BSZ*N_KVH*HD*(SEQ/2)];           // V^T fp16 hi
__device__ __align__(256) uint32_t g_Ah[ROWS * KP],   g_Al[ROWS * KP];    // attn out fp16 hi/lo

// ---------------- helpers ----------------------------------------------------
__device__ __forceinline__ void split_pack(float x, float y, uint32_t& hv, uint32_t& lv) {
    __half2 hb = __floats2half2_rn(x, y);
    hv = *reinterpret_cast<uint32_t*>(&hb);
    float rx = x - __half2float(__low2half(hb));
    float ry = y - __half2float(__high2half(hb));
    __half2 lb = __floats2half2_rn(rx, ry);
    lv = *reinterpret_cast<uint32_t*>(&lb);
}

__device__ __forceinline__ uint32_t pack_h(float x, float y) {
    __half2 hb = __floats2half2_rn(x, y);
    return *reinterpret_cast<uint32_t*>(&hb);
}

__device__ __forceinline__ void mma_f16(float* c,
        uint32_t a0, uint32_t a1, uint32_t a2, uint32_t a3,
        uint32_t b0, uint32_t b1) {
    asm volatile(
        "mma.sync.aligned.m16n8k16.row.col.f32.f16.f16.f32 "
        "{%0,%1,%2,%3}, {%4,%5,%6,%7}, {%8,%9}, {%0,%1,%2,%3};"
        : "+f"(c[0]), "+f"(c[1]), "+f"(c[2]), "+f"(c[3])
        : "r"(a0), "r"(a1), "r"(a2), "r"(a3), "r"(b0), "r"(b1));
}

__device__ __forceinline__ void ldm4(uint32_t* r, uint32_t addr) {
    asm volatile("ldmatrix.sync.aligned.m8n8.x4.shared.b16 {%0,%1,%2,%3}, [%4];"
                 : "=r"(r[0]), "=r"(r[1]), "=r"(r[2]), "=r"(r[3]) : "r"(addr));
}

__device__ __forceinline__ float ex2(float x) {
    float y;
    asm("ex2.approx.ftz.f32 %0, %1;" : "=f"(y) : "f"(x));
    return y;
}

__device__ __forceinline__ void cpa16(uint32_t dst_smem, const void* src) {
    asm volatile("cp.async.cg.shared.global [%0], [%1], 16;\n"
                 :: "r"(dst_smem), "l"(src));
}
#define CP_COMMIT asm volatile("cp.async.commit_group;\n" ::)
#define CP_WAIT0  asm volatile("cp.async.wait_group 0;\n" ::)
#define CP_WAIT1  asm volatile("cp.async.wait_group 1;\n" ::)

// rope + fp16 split store of a (even,odd) column pair
__device__ __forceinline__ void rope_split_store(
        uint32_t* __restrict__ dh, uint32_t* __restrict__ dl, int ldp,
        int row, int col, float2 v,
        const float* __restrict__ cs, const float* __restrict__ sn) {
    int s = row & (SEQ - 1);
    int p = (col & 63) >> 1;
    float c = cs[s * 32 + p], si = sn[s * 32 + p];
    float orr = v.x * c - v.y * si;
    float oi  = v.x * si + v.y * c;
    uint32_t h, l;
    split_pack(orr, oi, h, l);
    size_t o = (size_t)row * ldp + (col >> 1);
    dh[o] = h; dl[o] = l;
}

// rope + fp16 hi-only store (K)
__device__ __forceinline__ void rope_store_h(
        uint32_t* __restrict__ dh, int ldp,
        int row, int col, float2 v,
        const float* __restrict__ cs, const float* __restrict__ sn) {
    int s = row & (SEQ - 1);
    int p = (col & 63) >> 1;
    float c = cs[s * 32 + p], si = sn[s * 32 + p];
    dh[(size_t)row * ldp + (col >> 1)] =
        pack_h(v.x * c - v.y * si, v.x * si + v.y * c);
}

// ---------------- conversion kernels ----------------------------------------
__global__ void conv_x(const float* __restrict__ x,
                       uint32_t* __restrict__ xh, uint32_t* __restrict__ xl,
                       int npairs) {
    int i = blockIdx.x * blockDim.x + threadIdx.x;
    if (i >= npairs) return;
    float2 v = *(const float2*)(x + 2 * (size_t)i);
    uint32_t h, l;
    split_pack(v.x, v.y, h, l);
    xh[i] = h; xl[i] = l;
}

// weight transposes: fp16 hi only, pre-scaled x64 (epilogue multiplies 1/64)
__global__ __launch_bounds__(256) void tconv_all(
        const float* __restrict__ wq, const float* __restrict__ wk,
        const float* __restrict__ wv, const float* __restrict__ wo,
        uint32_t* __restrict__ Th, uint32_t* __restrict__ Oh) {
    __shared__ float s[64][33];
    const int tid = threadIdx.x;
    const int bx = blockIdx.x, k0 = blockIdx.y * 64;
    const float* W; int N, rowoff, nb;
    uint32_t* Dh;
    if (bx < 64)       { W = wq; N = DIM;   rowoff = 0;           nb = bx;      Dh = Th; }
    else if (bx < 80)  { W = wk; N = KVDIM; rowoff = DIM;         nb = bx - 64; Dh = Th; }
    else if (bx < 96)  { W = wv; N = KVDIM; rowoff = DIM + KVDIM; nb = bx - 80; Dh = Th; }
    else               { W = wo; N = DIM;   rowoff = 0;           nb = bx - 96; Dh = Oh; }
    const int n0 = nb * 32;
    #pragma unroll
    for (int jj = 0; jj < 8; jj++) {
        int id = tid + 256 * jj;
        int k = id >> 5, n = id & 31;
        s[k][n] = W[(size_t)(k0 + k) * N + n0 + n];
    }
    __syncthreads();
    #pragma unroll
    for (int jj = 0; jj < 4; jj++) {
        int id = tid + 256 * jj;
        int n = id >> 5, kp = id & 31;
        size_t o = (size_t)(rowoff + n0 + n) * KP + (k0 >> 1) + kp;
        Dh[o] = pack_h(s[2 * kp][n] * 64.f, s[2 * kp + 1][n] * 64.f);
    }
}

__global__ __launch_bounds__(256) void vt_conv(const float* __restrict__ V,
                                               uint32_t* __restrict__ Vth) {
    __shared__ float s[32][65];
    const int tid = threadIdx.x;
    const int s0 = blockIdx.x * 32;
    const int bz = blockIdx.z;
    const int b = bz >> 3, kvh = bz & 7;
    #pragma unroll
    for (int jj = 0; jj < 8; jj++) {
        int id = tid + 256 * jj;
        int si = id >> 6, d = id & 63;
        s[si][d] = V[(size_t)(b * SEQ + s0 + si) * KVDIM + kvh * HD + d];
    }
    __syncthreads();
    #pragma unroll
    for (int jj = 0; jj < 4; jj++) {
        int id = tid + 256 * jj;
        int d = id >> 4, sp = id & 15;
        size_t o = (size_t)(bz * HD + d) * (SEQ / 2) + (s0 >> 1) + sp;
        Vth[o] = pack_h(s[2 * sp][d], s[2 * sp + 1][d]);
    }
}

// ---------------- fp16 GEMM (2-mma: (Ah+Al) @ Bh) ---------------------------
// 128x128 tile, BK=32, 256 threads; 3 staged arrays (AH|AL|BH) = 60 KB smem.
#define SG        20
#define TBUF_U32  (3 * 128 * SG)
#define TBUF_B    (TBUF_U32 * 4)        // 30720 bytes per stage
#define AREA_AL   (128 * SG * 4)
#define AREA_BH   (2 * 128 * SG * 4)

template <bool QKV>
__global__ __launch_bounds__(256) void gemm_f16(
        const uint32_t* __restrict__ Ah, const uint32_t* __restrict__ Al,
        const uint32_t* __restrict__ Bh,
        float* __restrict__ Cout,
        const float* __restrict__ cs, const float* __restrict__ sn, int K) {
    extern __shared__ uint32_t sm[];
    const int KPL = K >> 1;
    const int tid = threadIdx.x;
    const int warp = tid >> 5, lane = tid & 31;
    const int tg = lane >> 2, t4 = lane & 3;
    const int wm = (warp >> 2) * 64;
    const int wn = (warp & 3) * 32;
    const int bx = blockIdx.x, by = blockIdx.y;

    const int mrow = ((lane >> 3) & 1) * 8 + (lane & 7);
    const int mcol = (lane >> 4) * 4;
    int aoff[4], boff[2];
    #pragma unroll
    for (int i = 0; i < 4; i++) aoff[i] = (wm + 16 * i + mrow) * SG + mcol;
    #pragma unroll
    for (int jj = 0; jj < 2; jj++) boff[jj] = (wn + 16 * jj + mrow) * SG + mcol;

    // cp.async slots: 3 arrays x 512 16B-chunks = 6 per thread
    const uint32_t* src[6];
    uint32_t dstoff[6];
    #pragma unroll
    for (int jj = 0; jj < 6; jj++) {
        int id = tid + 256 * jj;
        int arr = id >> 9, rem = id & 511;
        int row = rem >> 2, ch = rem & 3;
        const uint32_t* base =
            (arr == 0) ? Ah + (size_t)(by * 128 + row) * KPL :
            (arr == 1) ? Al + (size_t)(by * 128 + row) * KPL :
                         Bh + (size_t)(bx * 128 + row) * KPL;
        src[jj] = base + ch * 4;
        dstoff[jj] = arr * (128 * SG) + row * SG + ch * 4;
    }
    uint32_t sbase = (uint32_t)__cvta_generic_to_shared(sm);

    float acc[4][4][4];
    #pragma unroll
    for (int i = 0; i < 4; i++)
        #pragma unroll
        for (int j = 0; j < 4; j++)
            #pragma unroll
            for (int c = 0; c < 4; c++) acc[i][j][c] = 0.f;

    const int nk = K >> 5;

    #pragma unroll
    for (int jj = 0; jj < 6; jj++)
        cpa16(sbase + dstoff[jj] * 4, src[jj]);
    CP_COMMIT;

    for (int kc = 0; kc < nk; kc++) {
        int cur = kc & 1;
        if (kc + 1 < nk) {
            uint32_t bb = sbase + (cur ^ 1) * TBUF_B;
            int kadv = (kc + 1) * 16;
            #pragma unroll
            for (int jj = 0; jj < 6; jj++)
                cpa16(bb + dstoff[jj] * 4, src[jj] + kadv);
            CP_COMMIT;
            CP_WAIT1;
        } else {
            CP_WAIT0;
        }
        __syncthreads();

        uint32_t bb = sbase + cur * TBUF_B;
        #pragma unroll
        for (int s = 0; s < 2; s++) {
            uint32_t aH[4][4], aL[4][4];
            #pragma unroll
            for (int i = 0; i < 4; i++) {
                ldm4(aH[i], bb + (aoff[i] + 8 * s) * 4);
                ldm4(aL[i], bb + AREA_AL + (aoff[i] + 8 * s) * 4);
            }
            #pragma unroll
            for (int jj = 0; jj < 2; jj++) {
                uint32_t bh[4];
                ldm4(bh, bb + AREA_BH + (boff[jj] + 8 * s) * 4);
                #pragma unroll
                for (int i = 0; i < 4; i++) {
                    float* c0 = acc[i][2 * jj];
                    float* c1 = acc[i][2 * jj + 1];
                    mma_f16(c0, aH[i][0], aH[i][1], aH[i][2], aH[i][3], bh[0], bh[2]);
                    mma_f16(c0, aL[i][0], aL[i][1], aL[i][2], aL[i][3], bh[0], bh[2]);
                    mma_f16(c1, aH[i][0], aH[i][1], aH[i][2], aH[i][3], bh[1], bh[3]);
                    mma_f16(c1, aL[i][0], aL[i][1], aL[i][2], aL[i][3], bh[1], bh[3]);
                }
            }
        }
        __syncthreads();
    }

    // ---- epilogue (undo x64 weight scaling) ----
    const float INV = 1.f / 64.f;
    #pragma unroll
    for (int i = 0; i < 4; i++) {
        int r0 = by * 128 + wm + 16 * i + tg;
        #pragma unroll
        for (int j = 0; j < 4; j++) {
            int col = bx * 128 + wn + 8 * j + 2 * t4;
            float2 v0 = make_float2(acc[i][j][0] * INV, acc[i][j][1] * INV);
            float2 v1 = make_float2(acc[i][j][2] * INV, acc[i][j][3] * INV);
            if (QKV) {
                if (col < DIM) {
                    rope_split_store(g_Qh, g_Ql, KP, r0, col, v0, cs, sn);
                    rope_split_store(g_Qh, g_Ql, KP, r0 + 8, col, v1, cs, sn);
                } else if (col < DIM + KVDIM) {
                    int c2 = col - DIM;
                    rope_store_h(g_Kh, KVP, r0, c2, v0, cs, sn);
                    rope_store_h(g_Kh, KVP, r0 + 8, c2, v1, cs, sn);
                } else {
                    int c2 = col - DIM - KVDIM;
                    *(float2*)(g_V + (size_t)r0 * KVDIM + c2) = v0;
                    *(float2*)(g_V + (size_t)(r0 + 8) * KVDIM + c2) = v1;
                }
            } else {
                *(float2*)(Cout + (size_t)r0 * DIM + col) = v0;
                *(float2*)(Cout + (size_t)(r0 + 8) * DIM + col) = v1;
            }
        }
    }
}

// ---------------- causal flash attention (fp16 2-mma) ------------------------
// S = (Qh+Ql)@Kh, O += (Ph+Pl)@Vh. 2 staged arrays (KH,VH): smem = 36,864 B.
#define SAT   36
#define KVBUF (2 * 64 * SAT)

__global__ __launch_bounds__(256) void attn_mma() {
    extern __shared__ uint32_t smu[];

    const int qt = (int)gridDim.x - 1 - (int)blockIdx.x;   // heavy tiles first
    const int h = blockIdx.y, b = blockIdx.z;
    const int kvh = h >> 2;
    const int tid = threadIdx.x;
    const int w = tid >> 5, lane = tid & 31;
    const int tg = lane >> 2, t4 = lane & 3;
    const int rA = w * 16 + tg, rB = rA + 8;
    const int rowAg = b * SEQ + qt * 128 + rA;
    const int rowBg = rowAg + 8;
    const int wrowmax = qt * 128 + w * 16 + 15;

    const int mrow = ((lane >> 3) & 1) * 8 + (lane & 7);
    const int mcol = (lane >> 4) * 4;
    int nfoff[4];
    #pragma unroll
    for (int jj = 0; jj < 4; jj++) nfoff[jj] = (16 * jj + mrow) * SAT + mcol;

    // cp.async slots: 2 arrays (KH, VH) -> 4 slots/thread
    const uint32_t* src[4];
    int step[4];
    uint32_t dstoff[4];
    #pragma unroll
    for (int jj = 0; jj < 4; jj++) {
        int id = tid + 256 * jj;
        int arr = id >> 9, rem = id & 511;
        int row = rem >> 3, ch = rem & 7;
        const uint32_t* base;
        if (arr == 0) base = g_Kh + (size_t)(b * SEQ + row) * KVP + kvh * 32;
        else          base = g_Vth + (size_t)((b * 8 + kvh) * HD + row) * (SEQ / 2);
        src[jj] = base + ch * 4;
        step[jj] = (arr == 0) ? 64 * KVP : 32;
        dstoff[jj] = arr * (64 * SAT) + row * SAT + ch * 4;
    }
    uint32_t sbase = (uint32_t)__cvta_generic_to_shared(smu);

    uint32_t qH[4][4], qL[4][4];
    {
        const uint32_t* QA = g_Qh + (size_t)rowAg * KP + h * 32;
        const uint32_t* QB = g_Qh + (size_t)rowBg * KP + h * 32;
        const uint32_t* qA = g_Ql + (size_t)rowAg * KP + h * 32;
        const uint32_t* qB = g_Ql + (size_t)rowBg * KP + h * 32;
        #pragma unroll
        for (int s = 0; s < 4; s++) {
            qH[s][0] = QA[8 * s + t4];     qH[s][1] = QB[8 * s + t4];
            qH[s][2] = QA[8 * s + t4 + 4]; qH[s][3] = QB[8 * s + t4 + 4];
            qL[s][0] = qA[8 * s + t4];     qL[s][1] = qB[8 * s + t4];
            qL[s][2] = qA[8 * s + t4 + 4]; qL[s][3] = qB[8 * s + t4 + 4];
        }
    }

    float oacc[8][4];
    #pragma unroll
    for (int j = 0; j < 8; j++)
        #pragma unroll
        for (int c = 0; c < 4; c++) oacc[j][c] = 0.f;
    float mA = -1e30f, mB = -1e30f, lA = 0.f, lB = 0.f;
    const float SCL = 0.18033688011112042f;   // 0.125 * log2(e)

    const int nkb = 2 * qt + 2;

    #pragma unroll
    for (int jj = 0; jj < 4; jj++)
        cpa16(sbase + dstoff[jj] * 4, src[jj]);
    CP_COMMIT;

    for (int kb = 0; kb < nkb; kb++) {
        int cur = kb & 1;
        if (kb + 1 < nkb) {
            uint32_t boff = sbase + (cur ^ 1) * (KVBUF * 4);
            #pragma unroll
            for (int jj = 0; jj < 4; jj++)
                cpa16(boff + dstoff[jj] * 4, src[jj] + (size_t)(kb + 1) * step[jj]);
            CP_COMMIT;
            CP_WAIT1;
        } else {
            CP_WAIT0;
        }
        __syncthreads();

        if (kb * 64 <= wrowmax) {
            uint32_t kvb = sbase + cur * (KVBUF * 4);
            const uint32_t VHo = 64 * SAT * 4;

            // ---- S = (Qh+Ql) @ Kh ----
            float sacc[8][4];
            #pragma unroll
            for (int j = 0; j < 8; j++)
                #pragma unroll
                for (int c = 0; c < 4; c++) sacc[j][c] = 0.f;
            #pragma unroll
            for (int s = 0; s < 4; s++) {
                #pragma unroll
                for (int jj = 0; jj < 4; jj++) {
                    uint32_t kh[4];
                    ldm4(kh, kvb + (nfoff[jj] + 8 * s) * 4);
                    float* c0 = sacc[2 * jj];
                    float* c1 = sacc[2 * jj + 1];
                    mma_f16(c0, qH[s][0], qH[s][1], qH[s][2], qH[s][3], kh[0], kh[2]);
                    mma_f16(c0, qL[s][0], qL[s][1], qL[s][2], qL[s][3], kh[0], kh[2]);
                    mma_f16(c1, qH[s][0], qH[s][1], qH[s][2], qH[s][3], kh[1], kh[3]);
                    mma_f16(c1, qL[s][0], qL[s][1], qL[s][2], qL[s][3], kh[1], kh[3]);
                }
            }
            // causal mask on raw scores (diagonal tiles)
            if (kb >= 2 * qt) {
                int rGA = qt * 128 + rA, rGB = rGA + 8;
                #pragma unroll
                for (int j = 0; j < 8; j++) {
                    int c0 = kb * 64 + 8 * j + 2 * t4;
                    if (c0 > rGA)     sacc[j][0] = -1e30f;
                    if (c0 + 1 > rGA) sacc[j][1] = -1e30f;
                    if (c0 > rGB)     sacc[j][2] = -1e30f;
                    if (c0 + 1 > rGB) sacc[j][3] = -1e30f;
                }
            }

            // ---- online softmax ----
            float mxA = -1e30f, mxB = -1e30f;
            #pragma unroll
            for (int j = 0; j < 8; j++) {
                mxA = fmaxf(mxA, fmaxf(sacc[j][0], sacc[j][1]));
                mxB = fmaxf(mxB, fmaxf(sacc[j][2], sacc[j][3]));
            }
            mxA = fmaxf(mxA, __shfl_xor_sync(0xffffffffu, mxA, 1));
            mxA = fmaxf(mxA, __shfl_xor_sync(0xffffffffu, mxA, 2));
            mxB = fmaxf(mxB, __shfl_xor_sync(0xffffffffu, mxB, 1));
            mxB = fmaxf(mxB, __shfl_xor_sync(0xffffffffu, mxB, 2));
            float nmA = fmaxf(mA, mxA * SCL), nmB = fmaxf(mB, mxB * SCL);
            float aA = ex2(mA - nmA), aB = ex2(mB - nmB);
            mA = nmA; mB = nmB;
            float sumA = 0.f, sumB = 0.f;
            uint32_t ph01[8], ph23[8], pl01[8], pl23[8];
            #pragma unroll
            for (int j = 0; j < 8; j++) {
                float p0 = ex2(fmaf(sacc[j][0], SCL, -nmA));
                float p1 = ex2(fmaf(sacc[j][1], SCL, -nmA));
                float p2 = ex2(fmaf(sacc[j][2], SCL, -nmB));
                float p3 = ex2(fmaf(sacc[j][3], SCL, -nmB));
                sumA += p0 + p1; sumB += p2 + p3;
                split_pack(p0, p1, ph01[j], pl01[j]);
                split_pack(p2, p3, ph23[j], pl23[j]);
            }
            lA = lA * aA + sumA;
            lB = lB * aB + sumB;
            #pragma unroll
            for (int j = 0; j < 8; j++) {
                oacc[j][0] *= aA; oacc[j][1] *= aA;
                oacc[j][2] *= aB; oacc[j][3] *= aB;
            }

            // ---- O += (Ph+Pl) @ Vh ----
            #pragma unroll
            for (int s = 0; s < 4; s++) {
                uint32_t aH0 = ph01[2 * s],     aH1 = ph23[2 * s];
                uint32_t aH2 = ph01[2 * s + 1], aH3 = ph23[2 * s + 1];
                uint32_t aL0 = pl01[2 * s],     aL1 = pl23[2 * s];
                uint32_t aL2 = pl01[2 * s + 1], aL3 = pl23[2 * s + 1];
                #pragma unroll
                for (int jj = 0; jj < 4; jj++) {
                    uint32_t vh[4];
                    ldm4(vh, kvb + VHo + (nfoff[jj] + 8 * s) * 4);
                    float* c0 = oacc[2 * jj];
                    float* c1 = oacc[2 * jj + 1];
                    mma_f16(c0, aH0, aH1, aH2, aH3, vh[0], vh[2]);
                    mma_f16(c0, aL0, aL1, aL2, aL3, vh[0], vh[2]);
                    mma_f16(c1, aH0, aH1, aH2, aH3, vh[1], vh[3]);
                    mma_f16(c1, aL0, aL1, aL2, aL3, vh[1], vh[3]);
                }
            }
        }
        __syncthreads();
    }

    // final cross-thread l reduction
    lA += __shfl_xor_sync(0xffffffffu, lA, 1);
    lA += __shfl_xor_sync(0xffffffffu, lA, 2);
    lB += __shfl_xor_sync(0xffffffffu, lB, 1);
    lB += __shfl_xor_sync(0xffffffffu, lB, 2);

    float ilA = 1.f / lA, ilB = 1.f / lB;
    #pragma unroll
    for (int j = 0; j < 8; j++) {
        uint32_t hh, ll;
        size_t oA = (size_t)rowAg * KP + h * 32 + 4 * j + t4;
        size_t oB = (size_t)rowBg * KP + h * 32 + 4 * j + t4;
        split_pack(oacc[j][0] * ilA, oacc[j][1] * ilA, hh, ll);
        g_Ah[oA] = hh; g_Al[oA] = ll;
        split_pack(oacc[j][2] * ilB, oacc[j][3] * ilB, hh, ll);
        g_Ah[oB] = hh; g_Al[oB] = ll;
    }
}

// ---------------- launch ----------------------------------------------------
extern "C" void kernel_launch(void* const* d_in, const int* in_sizes, int n_in,
                              void* d_out, int out_size) {
    const float* x  = (const float*)d_in[0];
    const float* fc = (const float*)d_in[1];
    const float* fs = (const float*)d_in[2];
    const float* wq = (const float*)d_in[3];
    const float* wk = (const float*)d_in[4];
    const float* wv = (const float*)d_in[5];
    const float* wo = (const float*)d_in[6];
    float* out = (float*)d_out;

    void *pV, *pxh, *pxl, *pwh, *pwoh, *pVth, *pAh, *pAl;
    cudaGetSymbolAddress(&pV, g_V);
    cudaGetSymbolAddress(&pxh, g_xh);   cudaGetSymbolAddress(&pxl, g_xl);
    cudaGetSymbolAddress(&pwh, g_wTh);
    cudaGetSymbolAddress(&pwoh, g_woTh);
    cudaGetSymbolAddress(&pVth, g_Vth);
    cudaGetSymbolAddress(&pAh, g_Ah);   cudaGetSymbolAddress(&pAl, g_Al);

    // ---- one-shot conversions ----
    conv_x<<<(ROWS * KP + 255) / 256, 256>>>(x, (uint32_t*)pxh, (uint32_t*)pxl, ROWS * KP);
    tconv_all<<<dim3(160, DIM / 64), 256>>>(wq, wk, wv, wo,
                                            (uint32_t*)pwh, (uint32_t*)pwoh);

    size_t gsmem = 2 * TBUF_B;   // 61440 B
    cudaFuncSetAttribute(gemm_f16<true>,  cudaFuncAttributeMaxDynamicSharedMemorySize, (int)gsmem);
    cudaFuncSetAttribute(gemm_f16<false>, cudaFuncAttributeMaxDynamicSharedMemorySize, (int)gsmem);

    // ---- fused QKV projection (epilogue: 1/64 + rope + fp16 split) ----
    gemm_f16<true><<<dim3(NW / 128, ROWS / 128), 256, gsmem>>>(
        (uint32_t*)pxh, (uint32_t*)pxl, (uint32_t*)pwh,
        nullptr, fc, fs, DIM);

    // ---- V transpose (fp16 hi) ----
    vt_conv<<<dim3(SEQ / 32, 1, BSZ * N_KVH), 256>>>((float*)pV, (uint32_t*)pVth);

    // ---- attention ----
    {
        size_t smem = 2 * KVBUF * sizeof(uint32_t);  // 36864 B
        cudaFuncSetAttribute(attn_mma, cudaFuncAttributeMaxDynamicSharedMemorySize, (int)smem);
        attn_mma<<<dim3(SEQ / 128, N_HEADS, BSZ), 256, smem>>>();
    }

    // ---- output projection ----
    gemm_f16<false><<<dim3(DIM / 128, ROWS / 128), 256, gsmem>>>(
        (uint32_t*)pAh, (uint32_t*)pAl, (uint32_t*)pwoh,
        out, nullptr, nullptr, DIM);
}

// round 13
// speedup vs baseline: 1.4710x; 1.0582x over previous
#include <cuda_runtime.h>
#include <cuda_fp16.h>
#include <cstdint>

#define BSZ      2
#define SEQ      2048
#define DIM      2048
#define N_HEADS  32
#define N_KVH    8
#define HD       64
#define ROWS     (BSZ*SEQ)          // 4096
#define KVDIM    (N_KVH*HD)         // 512
#define KP       (DIM/2)            // 1024 u32 pairs per DIM row
#define KVP      (KVDIM/2)          // 256
#define NW       (DIM + 2*KVDIM)    // 3072 fused qkv width

// ---------------- scratch (device globals; no allocations allowed) ----------
__device__ __align__(256) uint32_t g_xh [ROWS * KP],  g_xl [ROWS * KP];   // x fp16 hi/lo
__device__ __align__(256) uint32_t g_wTh[NW * KP];                        // W^T fp16 hi (x64)
__device__ __align__(256) uint32_t g_woTh[DIM * KP];                      // Wo^T fp16 hi (x64)
__device__ __align__(256) uint32_t g_Qh[ROWS * KP],   g_Ql[ROWS * KP];    // Q fp16 hi/lo (roped)
__device__ __align__(256) uint32_t g_Kh[ROWS * KVP];                      // K fp16 hi (roped)
__device__ __align__(256) uint32_t g_Vth[BSZ*N_KVH*HD*(SEQ/2)];           // V^T fp16 hi
__device__ __align__(256) uint32_t g_Ah[ROWS * KP],   g_Al[ROWS * KP];    // attn out fp16 hi/lo

// ---------------- helpers ----------------------------------------------------
__device__ __forceinline__ void split_pack(float x, float y, uint32_t& hv, uint32_t& lv) {
    __half2 hb = __floats2half2_rn(x, y);
    hv = *reinterpret_cast<uint32_t*>(&hb);
    float rx = x - __half2float(__low2half(hb));
    float ry = y - __half2float(__high2half(hb));
    __half2 lb = __floats2half2_rn(rx, ry);
    lv = *reinterpret_cast<uint32_t*>(&lb);
}

__device__ __forceinline__ uint32_t pack_h(float x, float y) {
    __half2 hb = __floats2half2_rn(x, y);
    return *reinterpret_cast<uint32_t*>(&hb);
}

__device__ __forceinline__ void mma_f16(float* c,
        uint32_t a0, uint32_t a1, uint32_t a2, uint32_t a3,
        uint32_t b0, uint32_t b1) {
    asm volatile(
        "mma.sync.aligned.m16n8k16.row.col.f32.f16.f16.f32 "
        "{%0,%1,%2,%3}, {%4,%5,%6,%7}, {%8,%9}, {%0,%1,%2,%3};"
        : "+f"(c[0]), "+f"(c[1]), "+f"(c[2]), "+f"(c[3])
        : "r"(a0), "r"(a1), "r"(a2), "r"(a3), "r"(b0), "r"(b1));
}

__device__ __forceinline__ void ldm4(uint32_t* r, uint32_t addr) {
    asm volatile("ldmatrix.sync.aligned.m8n8.x4.shared.b16 {%0,%1,%2,%3}, [%4];"
                 : "=r"(r[0]), "=r"(r[1]), "=r"(r[2]), "=r"(r[3]) : "r"(addr));
}

__device__ __forceinline__ float ex2(float x) {
    float y;
    asm("ex2.approx.ftz.f32 %0, %1;" : "=f"(y) : "f"(x));
    return y;
}

__device__ __forceinline__ void cpa16(uint32_t dst_smem, const void* src) {
    asm volatile("cp.async.cg.shared.global [%0], [%1], 16;\n"
                 :: "r"(dst_smem), "l"(src));
}
#define CP_COMMIT asm volatile("cp.async.commit_group;\n" ::)
#define CP_WAIT0  asm volatile("cp.async.wait_group 0;\n" ::)
#define CP_WAIT1  asm volatile("cp.async.wait_group 1;\n" ::)

// rope + fp16 split store of a (even,odd) column pair
__device__ __forceinline__ void rope_split_store(
        uint32_t* __restrict__ dh, uint32_t* __restrict__ dl, int ldp,
        int row, int col, float2 v,
        const float* __restrict__ cs, const float* __restrict__ sn) {
    int s = row & (SEQ - 1);
    int p = (col & 63) >> 1;
    float c = cs[s * 32 + p], si = sn[s * 32 + p];
    float orr = v.x * c - v.y * si;
    float oi  = v.x * si + v.y * c;
    uint32_t h, l;
    split_pack(orr, oi, h, l);
    size_t o = (size_t)row * ldp + (col >> 1);
    dh[o] = h; dl[o] = l;
}

// rope + fp16 hi-only store (K)
__device__ __forceinline__ void rope_store_h(
        uint32_t* __restrict__ dh, int ldp,
        int row, int col, float2 v,
        const float* __restrict__ cs, const float* __restrict__ sn) {
    int s = row & (SEQ - 1);
    int p = (col & 63) >> 1;
    float c = cs[s * 32 + p], si = sn[s * 32 + p];
    dh[(size_t)row * ldp + (col >> 1)] =
        pack_h(v.x * c - v.y * si, v.x * si + v.y * c);
}

// V^T fp16 store: thread holds (d, d+1) of one sequence row; scatter 16-bit
__device__ __forceinline__ void vt_store(int row, int c2, float2 v) {
    int kvh = c2 >> 6, d = c2 & 63;
    int b = row >> 11, s = row & (SEQ - 1);
    int bz = b * 8 + kvh;
    uint16_t* vt = (uint16_t*)g_Vth;
    size_t base = ((size_t)(bz * HD + d) * (SEQ / 2) + (s >> 1)) * 2 + (s & 1);
    __half hx = __float2half_rn(v.x), hy = __float2half_rn(v.y);
    vt[base]       = *reinterpret_cast<uint16_t*>(&hx);
    vt[base + SEQ] = *reinterpret_cast<uint16_t*>(&hy);   // d+1 row of V^T
}

// ---------------- conversion kernels ----------------------------------------
__global__ void conv_x(const float* __restrict__ x,
                       uint32_t* __restrict__ xh, uint32_t* __restrict__ xl,
                       int npairs) {
    int i = blockIdx.x * blockDim.x + threadIdx.x;
    if (i >= npairs) return;
    float2 v = *(const float2*)(x + 2 * (size_t)i);
    uint32_t h, l;
    split_pack(v.x, v.y, h, l);
    xh[i] = h; xl[i] = l;
}

// weight transposes: fp16 hi only, pre-scaled x64 (epilogue multiplies 1/64)
__global__ __launch_bounds__(256) void tconv_all(
        const float* __restrict__ wq, const float* __restrict__ wk,
        const float* __restrict__ wv, const float* __restrict__ wo,
        uint32_t* __restrict__ Th, uint32_t* __restrict__ Oh) {
    __shared__ float s[64][33];
    const int tid = threadIdx.x;
    const int bx = blockIdx.x, k0 = blockIdx.y * 64;
    const float* W; int N, rowoff, nb;
    uint32_t* Dh;
    if (bx < 64)       { W = wq; N = DIM;   rowoff = 0;           nb = bx;      Dh = Th; }
    else if (bx < 80)  { W = wk; N = KVDIM; rowoff = DIM;         nb = bx - 64; Dh = Th; }
    else if (bx < 96)  { W = wv; N = KVDIM; rowoff = DIM + KVDIM; nb = bx - 80; Dh = Th; }
    else               { W = wo; N = DIM;   rowoff = 0;           nb = bx - 96; Dh = Oh; }
    const int n0 = nb * 32;
    #pragma unroll
    for (int jj = 0; jj < 8; jj++) {
        int id = tid + 256 * jj;
        int k = id >> 5, n = id & 31;
        s[k][n] = W[(size_t)(k0 + k) * N + n0 + n];
    }
    __syncthreads();
    #pragma unroll
    for (int jj = 0; jj < 4; jj++) {
        int id = tid + 256 * jj;
        int n = id >> 5, kp = id & 31;
        size_t o = (size_t)(rowoff + n0 + n) * KP + (k0 >> 1) + kp;
        Dh[o] = pack_h(s[2 * kp][n] * 64.f, s[2 * kp + 1][n] * 64.f);
    }
}

// ---------------- fp16 GEMM (2-mma: (Ah+Al) @ Bh) ---------------------------
// 128x128 tile, BK=32, 256 threads; 3 staged arrays (AH|AL|BH) = 60 KB smem.
#define SG        20
#define TBUF_U32  (3 * 128 * SG)
#define TBUF_B    (TBUF_U32 * 4)        // 30720 bytes per stage
#define AREA_AL   (128 * SG * 4)
#define AREA_BH   (2 * 128 * SG * 4)

template <bool QKV>
__global__ __launch_bounds__(256) void gemm_f16(
        const uint32_t* __restrict__ Ah, const uint32_t* __restrict__ Al,
        const uint32_t* __restrict__ Bh,
        float* __restrict__ Cout,
        const float* __restrict__ cs, const float* __restrict__ sn, int K) {
    extern __shared__ uint32_t sm[];
    const int KPL = K >> 1;
    const int tid = threadIdx.x;
    const int warp = tid >> 5, lane = tid & 31;
    const int tg = lane >> 2, t4 = lane & 3;
    const int wm = (warp >> 2) * 64;
    const int wn = (warp & 3) * 32;
    const int bx = blockIdx.x, by = blockIdx.y;

    const int mrow = ((lane >> 3) & 1) * 8 + (lane & 7);
    const int mcol = (lane >> 4) * 4;
    int aoff[4], boff[2];
    #pragma unroll
    for (int i = 0; i < 4; i++) aoff[i] = (wm + 16 * i + mrow) * SG + mcol;
    #pragma unroll
    for (int jj = 0; jj < 2; jj++) boff[jj] = (wn + 16 * jj + mrow) * SG + mcol;

    const uint32_t* src[6];
    uint32_t dstoff[6];
    #pragma unroll
    for (int jj = 0; jj < 6; jj++) {
        int id = tid + 256 * jj;
        int arr = id >> 9, rem = id & 511;
        int row = rem >> 2, ch = rem & 3;
        const uint32_t* base =
            (arr == 0) ? Ah + (size_t)(by * 128 + row) * KPL :
            (arr == 1) ? Al + (size_t)(by * 128 + row) * KPL :
                         Bh + (size_t)(bx * 128 + row) * KPL;
        src[jj] = base + ch * 4;
        dstoff[jj] = arr * (128 * SG) + row * SG + ch * 4;
    }
    uint32_t sbase = (uint32_t)__cvta_generic_to_shared(sm);

    float acc[4][4][4];
    #pragma unroll
    for (int i = 0; i < 4; i++)
        #pragma unroll
        for (int j = 0; j < 4; j++)
            #pragma unroll
            for (int c = 0; c < 4; c++) acc[i][j][c] = 0.f;

    const int nk = K >> 5;

    #pragma unroll
    for (int jj = 0; jj < 6; jj++)
        cpa16(sbase + dstoff[jj] * 4, src[jj]);
    CP_COMMIT;

    for (int kc = 0; kc < nk; kc++) {
        int cur = kc & 1;
        if (kc + 1 < nk) {
            uint32_t bb = sbase + (cur ^ 1) * TBUF_B;
            int kadv = (kc + 1) * 16;
            #pragma unroll
            for (int jj = 0; jj < 6; jj++)
                cpa16(bb + dstoff[jj] * 4, src[jj] + kadv);
            CP_COMMIT;
            CP_WAIT1;
        } else {
            CP_WAIT0;
        }
        __syncthreads();

        uint32_t bb = sbase + cur * TBUF_B;
        #pragma unroll
        for (int s = 0; s < 2; s++) {
            uint32_t aH[4][4], aL[4][4];
            #pragma unroll
            for (int i = 0; i < 4; i++) {
                ldm4(aH[i], bb + (aoff[i] + 8 * s) * 4);
                ldm4(aL[i], bb + AREA_AL + (aoff[i] + 8 * s) * 4);
            }
            #pragma unroll
            for (int jj = 0; jj < 2; jj++) {
                uint32_t bh[4];
                ldm4(bh, bb + AREA_BH + (boff[jj] + 8 * s) * 4);
                #pragma unroll
                for (int i = 0; i < 4; i++) {
                    float* c0 = acc[i][2 * jj];
                    float* c1 = acc[i][2 * jj + 1];
                    mma_f16(c0, aH[i][0], aH[i][1], aH[i][2], aH[i][3], bh[0], bh[2]);
                    mma_f16(c0, aL[i][0], aL[i][1], aL[i][2], aL[i][3], bh[0], bh[2]);
                    mma_f16(c1, aH[i][0], aH[i][1], aH[i][2], aH[i][3], bh[1], bh[3]);
                    mma_f16(c1, aL[i][0], aL[i][1], aL[i][2], aL[i][3], bh[1], bh[3]);
                }
            }
        }
        __syncthreads();
    }

    // ---- epilogue (undo x64 weight scaling) ----
    const float INV = 1.f / 64.f;
    #pragma unroll
    for (int i = 0; i < 4; i++) {
        int r0 = by * 128 + wm + 16 * i + tg;
        #pragma unroll
        for (int j = 0; j < 4; j++) {
            int col = bx * 128 + wn + 8 * j + 2 * t4;
            float2 v0 = make_float2(acc[i][j][0] * INV, acc[i][j][1] * INV);
            float2 v1 = make_float2(acc[i][j][2] * INV, acc[i][j][3] * INV);
            if (QKV) {
                if (col < DIM) {
                    rope_split_store(g_Qh, g_Ql, KP, r0, col, v0, cs, sn);
                    rope_split_store(g_Qh, g_Ql, KP, r0 + 8, col, v1, cs, sn);
                } else if (col < DIM + KVDIM) {
                    int c2 = col - DIM;
                    rope_store_h(g_Kh, KVP, r0, c2, v0, cs, sn);
                    rope_store_h(g_Kh, KVP, r0 + 8, c2, v1, cs, sn);
                } else {
                    int c2 = col - DIM - KVDIM;
                    vt_store(r0, c2, v0);
                    vt_store(r0 + 8, c2, v1);
                }
            } else {
                *(float2*)(Cout + (size_t)r0 * DIM + col) = v0;
                *(float2*)(Cout + (size_t)(r0 + 8) * DIM + col) = v1;
            }
        }
    }
}

// ---------------- causal flash attention (fp16) ------------------------------
// S = (Qh+Ql)@Kh; O += Ph@Vh (P hi-only: P in [0,1], fp16 rel ~2^-11).
// 2 staged arrays (KH,VH): smem = 36,864 B.
#define SAT   36
#define KVBUF (2 * 64 * SAT)

__global__ __launch_bounds__(256) void attn_mma() {
    extern __shared__ uint32_t smu[];

    const int qt = (int)gridDim.x - 1 - (int)blockIdx.x;   // heavy tiles first
    const int h = blockIdx.y, b = blockIdx.z;
    const int kvh = h >> 2;
    const int tid = threadIdx.x;
    const int w = tid >> 5, lane = tid & 31;
    const int tg = lane >> 2, t4 = lane & 3;
    const int rA = w * 16 + tg, rB = rA + 8;
    const int rowAg = b * SEQ + qt * 128 + rA;
    const int rowBg = rowAg + 8;
    const int wrowmax = qt * 128 + w * 16 + 15;

    const int mrow = ((lane >> 3) & 1) * 8 + (lane & 7);
    const int mcol = (lane >> 4) * 4;
    int nfoff[4];
    #pragma unroll
    for (int jj = 0; jj < 4; jj++) nfoff[jj] = (16 * jj + mrow) * SAT + mcol;

    const uint32_t* src[4];
    int step[4];
    uint32_t dstoff[4];
    #pragma unroll
    for (int jj = 0; jj < 4; jj++) {
        int id = tid + 256 * jj;
        int arr = id >> 9, rem = id & 511;
        int row = rem >> 3, ch = rem & 7;
        const uint32_t* base;
        if (arr == 0) base = g_Kh + (size_t)(b * SEQ + row) * KVP + kvh * 32;
        else          base = g_Vth + (size_t)((b * 8 + kvh) * HD + row) * (SEQ / 2);
        src[jj] = base + ch * 4;
        step[jj] = (arr == 0) ? 64 * KVP : 32;
        dstoff[jj] = arr * (64 * SAT) + row * SAT + ch * 4;
    }
    uint32_t sbase = (uint32_t)__cvta_generic_to_shared(smu);

    uint32_t qH[4][4], qL[4][4];
    {
        const uint32_t* QA = g_Qh + (size_t)rowAg * KP + h * 32;
        const uint32_t* QB = g_Qh + (size_t)rowBg * KP + h * 32;
        const uint32_t* qA = g_Ql + (size_t)rowAg * KP + h * 32;
        const uint32_t* qB = g_Ql + (size_t)rowBg * KP + h * 32;
        #pragma unroll
        for (int s = 0; s < 4; s++) {
            qH[s][0] = QA[8 * s + t4];     qH[s][1] = QB[8 * s + t4];
            qH[s][2] = QA[8 * s + t4 + 4]; qH[s][3] = QB[8 * s + t4 + 4];
            qL[s][0] = qA[8 * s + t4];     qL[s][1] = qB[8 * s + t4];
            qL[s][2] = qA[8 * s + t4 + 4]; qL[s][3] = qB[8 * s + t4 + 4];
        }
    }

    float oacc[8][4];
    #pragma unroll
    for (int j = 0; j < 8; j++)
        #pragma unroll
        for (int c = 0; c < 4; c++) oacc[j][c] = 0.f;
    float mA = -1e30f, mB = -1e30f, lA = 0.f, lB = 0.f;
    const float SCL = 0.18033688011112042f;   // 0.125 * log2(e)

    const int nkb = 2 * qt + 2;

    #pragma unroll
    for (int jj = 0; jj < 4; jj++)
        cpa16(sbase + dstoff[jj] * 4, src[jj]);
    CP_COMMIT;

    for (int kb = 0; kb < nkb; kb++) {
        int cur = kb & 1;
        if (kb + 1 < nkb) {
            uint32_t boff = sbase + (cur ^ 1) * (KVBUF * 4);
            #pragma unroll
            for (int jj = 0; jj < 4; jj++)
                cpa16(boff + dstoff[jj] * 4, src[jj] + (size_t)(kb + 1) * step[jj]);
            CP_COMMIT;
            CP_WAIT1;
        } else {
            CP_WAIT0;
        }
        __syncthreads();

        if (kb * 64 <= wrowmax) {
            uint32_t kvb = sbase + cur * (KVBUF * 4);
            const uint32_t VHo = 64 * SAT * 4;

            // ---- S = (Qh+Ql) @ Kh ----
            float sacc[8][4];
            #pragma unroll
            for (int j = 0; j < 8; j++)
                #pragma unroll
                for (int c = 0; c < 4; c++) sacc[j][c] = 0.f;
            #pragma unroll
            for (int s = 0; s < 4; s++) {
                #pragma unroll
                for (int jj = 0; jj < 4; jj++) {
                    uint32_t kh[4];
                    ldm4(kh, kvb + (nfoff[jj] + 8 * s) * 4);
                    float* c0 = sacc[2 * jj];
                    float* c1 = sacc[2 * jj + 1];
                    mma_f16(c0, qH[s][0], qH[s][1], qH[s][2], qH[s][3], kh[0], kh[2]);
                    mma_f16(c0, qL[s][0], qL[s][1], qL[s][2], qL[s][3], kh[0], kh[2]);
                    mma_f16(c1, qH[s][0], qH[s][1], qH[s][2], qH[s][3], kh[1], kh[3]);
                    mma_f16(c1, qL[s][0], qL[s][1], qL[s][2], qL[s][3], kh[1], kh[3]);
                }
            }
            // causal mask on raw scores (diagonal tiles)
            if (kb >= 2 * qt) {
                int rGA = qt * 128 + rA, rGB = rGA + 8;
                #pragma unroll
                for (int j = 0; j < 8; j++) {
                    int c0 = kb * 64 + 8 * j + 2 * t4;
                    if (c0 > rGA)     sacc[j][0] = -1e30f;
                    if (c0 + 1 > rGA) sacc[j][1] = -1e30f;
                    if (c0 > rGB)     sacc[j][2] = -1e30f;
                    if (c0 + 1 > rGB) sacc[j][3] = -1e30f;
                }
            }

            // ---- online softmax ----
            float mxA = -1e30f, mxB = -1e30f;
            #pragma unroll
            for (int j = 0; j < 8; j++) {
                mxA = fmaxf(mxA, fmaxf(sacc[j][0], sacc[j][1]));
                mxB = fmaxf(mxB, fmaxf(sacc[j][2], sacc[j][3]));
            }
            mxA = fmaxf(mxA, __shfl_xor_sync(0xffffffffu, mxA, 1));
            mxA = fmaxf(mxA, __shfl_xor_sync(0xffffffffu, mxA, 2));
            mxB = fmaxf(mxB, __shfl_xor_sync(0xffffffffu, mxB, 1));
            mxB = fmaxf(mxB, __shfl_xor_sync(0xffffffffu, mxB, 2));
            float nmA = fmaxf(mA, mxA * SCL), nmB = fmaxf(mB, mxB * SCL);
            float aA = ex2(mA - nmA), aB = ex2(mB - nmB);
            mA = nmA; mB = nmB;
            float sumA = 0.f, sumB = 0.f;
            uint32_t ph01[8], ph23[8];
            #pragma unroll
            for (int j = 0; j < 8; j++) {
                float p0 = ex2(fmaf(sacc[j][0], SCL, -nmA));
                float p1 = ex2(fmaf(sacc[j][1], SCL, -nmA));
                float p2 = ex2(fmaf(sacc[j][2], SCL, -nmB));
                float p3 = ex2(fmaf(sacc[j][3], SCL, -nmB));
                sumA += p0 + p1; sumB += p2 + p3;
                ph01[j] = pack_h(p0, p1);
                ph23[j] = pack_h(p2, p3);
            }
            lA = lA * aA + sumA;
            lB = lB * aB + sumB;
            #pragma unroll
            for (int j = 0; j < 8; j++) {
                oacc[j][0] *= aA; oacc[j][1] *= aA;
                oacc[j][2] *= aB; oacc[j][3] *= aB;
            }

            // ---- O += Ph @ Vh ----
            #pragma unroll
            for (int s = 0; s < 4; s++) {
                uint32_t aH0 = ph01[2 * s],     aH1 = ph23[2 * s];
                uint32_t aH2 = ph01[2 * s + 1], aH3 = ph23[2 * s + 1];
                #pragma unroll
                for (int jj = 0; jj < 4; jj++) {
                    uint32_t vh[4];
                    ldm4(vh, kvb + VHo + (nfoff[jj] + 8 * s) * 4);
                    mma_f16(oacc[2 * jj],     aH0, aH1, aH2, aH3, vh[0], vh[2]);
                    mma_f16(oacc[2 * jj + 1], aH0, aH1, aH2, aH3, vh[1], vh[3]);
                }
            }
        }
        __syncthreads();
    }

    // final cross-thread l reduction
    lA += __shfl_xor_sync(0xffffffffu, lA, 1);
    lA += __shfl_xor_sync(0xffffffffu, lA, 2);
    lB += __shfl_xor_sync(0xffffffffu, lB, 1);
    lB += __shfl_xor_sync(0xffffffffu, lB, 2);

    float ilA = 1.f / lA, ilB = 1.f / lB;
    #pragma unroll
    for (int j = 0; j < 8; j++) {
        uint32_t hh, ll;
        size_t oA = (size_t)rowAg * KP + h * 32 + 4 * j + t4;
        size_t oB = (size_t)rowBg * KP + h * 32 + 4 * j + t4;
        split_pack(oacc[j][0] * ilA, oacc[j][1] * ilA, hh, ll);
        g_Ah[oA] = hh; g_Al[oA] = ll;
        split_pack(oacc[j][2] * ilB, oacc[j][3] * ilB, hh, ll);
        g_Ah[oB] = hh; g_Al[oB] = ll;
    }
}

// ---------------- launch ----------------------------------------------------
extern "C" void kernel_launch(void* const* d_in, const int* in_sizes, int n_in,
                              void* d_out, int out_size) {
    const float* x  = (const float*)d_in[0];
    const float* fc = (const float*)d_in[1];
    const float* fs = (const float*)d_in[2];
    const float* wq = (const float*)d_in[3];
    const float* wk = (const float*)d_in[4];
    const float* wv = (const float*)d_in[5];
    const float* wo = (const float*)d_in[6];
    float* out = (float*)d_out;

    void *pxh, *pxl, *pwh, *pwoh, *pAh, *pAl;
    cudaGetSymbolAddress(&pxh, g_xh);   cudaGetSymbolAddress(&pxl, g_xl);
    cudaGetSymbolAddress(&pwh, g_wTh);
    cudaGetSymbolAddress(&pwoh, g_woTh);
    cudaGetSymbolAddress(&pAh, g_Ah);   cudaGetSymbolAddress(&pAl, g_Al);

    // ---- one-shot conversions ----
    conv_x<<<(ROWS * KP + 255) / 256, 256>>>(x, (uint32_t*)pxh, (uint32_t*)pxl, ROWS * KP);
    tconv_all<<<dim3(160, DIM / 64), 256>>>(wq, wk, wv, wo,
                                            (uint32_t*)pwh, (uint32_t*)pwoh);

    size_t gsmem = 2 * TBUF_B;   // 61440 B
    cudaFuncSetAttribute(gemm_f16<true>,  cudaFuncAttributeMaxDynamicSharedMemorySize, (int)gsmem);
    cudaFuncSetAttribute(gemm_f16<false>, cudaFuncAttributeMaxDynamicSharedMemorySize, (int)gsmem);

    // ---- fused QKV projection (epilogue: 1/64 + rope/split + V^T fp16) ----
    gemm_f16<true><<<dim3(NW / 128, ROWS / 128), 256, gsmem>>>(
        (uint32_t*)pxh, (uint32_t*)pxl, (uint32_t*)pwh,
        nullptr, fc, fs, DIM);

    // ---- attention ----
    {
        size_t smem = 2 * KVBUF * sizeof(uint32_t);  // 36864 B
        cudaFuncSetAttribute(attn_mma, cudaFuncAttributeMaxDynamicSharedMemorySize, (int)smem);
        attn_mma<<<dim3(SEQ / 128, N_HEADS, BSZ), 256, smem>>>();
    }

    // ---- output projection ----
    gemm_f16<false><<<dim3(DIM / 128, ROWS / 128), 256, gsmem>>>(
        (uint32_t*)pAh, (uint32_t*)pAl, (uint32_t*)pwoh,
        out, nullptr, nullptr, DIM);
}

// round 14
// speedup vs baseline: 1.5119x; 1.0278x over previous
#include <cuda_runtime.h>
#include <cuda_fp16.h>
#include <cstdint>

#define BSZ      2
#define SEQ      2048
#define DIM      2048
#define N_HEADS  32
#define N_KVH    8
#define HD       64
#define ROWS     (BSZ*SEQ)          // 4096
#define KVDIM    (N_KVH*HD)         // 512
#define KP       (DIM/2)            // 1024 u32 pairs per DIM row
#define KVP      (KVDIM/2)          // 256
#define NW       (DIM + 2*KVDIM)    // 3072 fused qkv width

// ---------------- scratch (device globals; no allocations allowed) ----------
__device__ __align__(256) uint32_t g_xh [ROWS * KP],  g_xl [ROWS * KP];   // x fp16 hi/lo
__device__ __align__(256) uint32_t g_wTh[NW * KP];                        // W^T fp16 hi (x64)
__device__ __align__(256) uint32_t g_woTh[DIM * KP];                      // Wo^T fp16 hi (x64)
__device__ __align__(256) uint32_t g_Qh[ROWS * KP],   g_Ql[ROWS * KP];    // Q fp16 hi/lo (roped)
__device__ __align__(256) uint32_t g_Kh[ROWS * KVP];                      // K fp16 hi (roped)
__device__ __align__(256) uint32_t g_Vth[BSZ*N_KVH*HD*(SEQ/2)];           // V^T fp16 hi
__device__ __align__(256) uint32_t g_Ah[ROWS * KP],   g_Al[ROWS * KP];    // attn out fp16 hi/lo

// ---------------- helpers ----------------------------------------------------
__device__ __forceinline__ void split_pack(float x, float y, uint32_t& hv, uint32_t& lv) {
    __half2 hb = __floats2half2_rn(x, y);
    hv = *reinterpret_cast<uint32_t*>(&hb);
    float rx = x - __half2float(__low2half(hb));
    float ry = y - __half2float(__high2half(hb));
    __half2 lb = __floats2half2_rn(rx, ry);
    lv = *reinterpret_cast<uint32_t*>(&lb);
}

__device__ __forceinline__ uint32_t pack_h(float x, float y) {
    __half2 hb = __floats2half2_rn(x, y);
    return *reinterpret_cast<uint32_t*>(&hb);
}

__device__ __forceinline__ void mma_f16(float* c,
        uint32_t a0, uint32_t a1, uint32_t a2, uint32_t a3,
        uint32_t b0, uint32_t b1) {
    asm volatile(
        "mma.sync.aligned.m16n8k16.row.col.f32.f16.f16.f32 "
        "{%0,%1,%2,%3}, {%4,%5,%6,%7}, {%8,%9}, {%0,%1,%2,%3};"
        : "+f"(c[0]), "+f"(c[1]), "+f"(c[2]), "+f"(c[3])
        : "r"(a0), "r"(a1), "r"(a2), "r"(a3), "r"(b0), "r"(b1));
}

__device__ __forceinline__ void ldm4(uint32_t* r, uint32_t addr) {
    asm volatile("ldmatrix.sync.aligned.m8n8.x4.shared.b16 {%0,%1,%2,%3}, [%4];"
                 : "=r"(r[0]), "=r"(r[1]), "=r"(r[2]), "=r"(r[3]) : "r"(addr));
}

__device__ __forceinline__ float ex2(float x) {
    float y;
    asm("ex2.approx.ftz.f32 %0, %1;" : "=f"(y) : "f"(x));
    return y;
}

__device__ __forceinline__ void cpa16(uint32_t dst_smem, const void* src) {
    asm volatile("cp.async.cg.shared.global [%0], [%1], 16;\n"
                 :: "r"(dst_smem), "l"(src));
}
#define CP_COMMIT asm volatile("cp.async.commit_group;\n" ::)
#define CP_WAIT0  asm volatile("cp.async.wait_group 0;\n" ::)
#define CP_WAIT1  asm volatile("cp.async.wait_group 1;\n" ::)

// rope + fp16 split store of a (even,odd) column pair
__device__ __forceinline__ void rope_split_store(
        uint32_t* __restrict__ dh, uint32_t* __restrict__ dl, int ldp,
        int row, int col, float2 v,
        const float* __restrict__ cs, const float* __restrict__ sn) {
    int s = row & (SEQ - 1);
    int p = (col & 63) >> 1;
    float c = cs[s * 32 + p], si = sn[s * 32 + p];
    float orr = v.x * c - v.y * si;
    float oi  = v.x * si + v.y * c;
    uint32_t h, l;
    split_pack(orr, oi, h, l);
    size_t o = (size_t)row * ldp + (col >> 1);
    dh[o] = h; dl[o] = l;
}

// rope + fp16 hi-only store (K)
__device__ __forceinline__ void rope_store_h(
        uint32_t* __restrict__ dh, int ldp,
        int row, int col, float2 v,
        const float* __restrict__ cs, const float* __restrict__ sn) {
    int s = row & (SEQ - 1);
    int p = (col & 63) >> 1;
    float c = cs[s * 32 + p], si = sn[s * 32 + p];
    dh[(size_t)row * ldp + (col >> 1)] =
        pack_h(v.x * c - v.y * si, v.x * si + v.y * c);
}

// V^T fp16 store: thread holds (d, d+1) of one sequence row; scatter 16-bit
__device__ __forceinline__ void vt_store(int row, int c2, float2 v) {
    int kvh = c2 >> 6, d = c2 & 63;
    int b = row >> 11, s = row & (SEQ - 1);
    int bz = b * 8 + kvh;
    uint16_t* vt = (uint16_t*)g_Vth;
    size_t base = ((size_t)(bz * HD + d) * (SEQ / 2) + (s >> 1)) * 2 + (s & 1);
    __half hx = __float2half_rn(v.x), hy = __float2half_rn(v.y);
    vt[base]       = *reinterpret_cast<uint16_t*>(&hx);
    vt[base + SEQ] = *reinterpret_cast<uint16_t*>(&hy);   // d+1 row of V^T
}

// ---------------- conversion kernels ----------------------------------------
__global__ void conv_x(const float* __restrict__ x,
                       uint32_t* __restrict__ xh, uint32_t* __restrict__ xl,
                       int npairs) {
    int i = blockIdx.x * blockDim.x + threadIdx.x;
    if (i >= npairs) return;
    float2 v = *(const float2*)(x + 2 * (size_t)i);
    uint32_t h, l;
    split_pack(v.x, v.y, h, l);
    xh[i] = h; xl[i] = l;
}

// weight transposes: fp16 hi only, pre-scaled x64 (epilogue multiplies 1/64)
__global__ __launch_bounds__(256) void tconv_all(
        const float* __restrict__ wq, const float* __restrict__ wk,
        const float* __restrict__ wv, const float* __restrict__ wo,
        uint32_t* __restrict__ Th, uint32_t* __restrict__ Oh) {
    __shared__ float s[64][33];
    const int tid = threadIdx.x;
    const int bx = blockIdx.x, k0 = blockIdx.y * 64;
    const float* W; int N, rowoff, nb;
    uint32_t* Dh;
    if (bx < 64)       { W = wq; N = DIM;   rowoff = 0;           nb = bx;      Dh = Th; }
    else if (bx < 80)  { W = wk; N = KVDIM; rowoff = DIM;         nb = bx - 64; Dh = Th; }
    else if (bx < 96)  { W = wv; N = KVDIM; rowoff = DIM + KVDIM; nb = bx - 80; Dh = Th; }
    else               { W = wo; N = DIM;   rowoff = 0;           nb = bx - 96; Dh = Oh; }
    const int n0 = nb * 32;
    #pragma unroll
    for (int jj = 0; jj < 8; jj++) {
        int id = tid + 256 * jj;
        int k = id >> 5, n = id & 31;
        s[k][n] = W[(size_t)(k0 + k) * N + n0 + n];
    }
    __syncthreads();
    #pragma unroll
    for (int jj = 0; jj < 4; jj++) {
        int id = tid + 256 * jj;
        int n = id >> 5, kp = id & 31;
        size_t o = (size_t)(rowoff + n0 + n) * KP + (k0 >> 1) + kp;
        Dh[o] = pack_h(s[2 * kp][n] * 64.f, s[2 * kp + 1][n] * 64.f);
    }
}

// ---------------- fp16 GEMM (2-mma: (Ah+Al) @ Bh) ---------------------------
// 128x128 tile, BK=32, 256 threads; 3 staged arrays (AH|AL|BH) = 60 KB smem.
#define SG        20
#define TBUF_U32  (3 * 128 * SG)
#define TBUF_B    (TBUF_U32 * 4)        // 30720 bytes per stage
#define AREA_AL   (128 * SG * 4)
#define AREA_BH   (2 * 128 * SG * 4)

template <bool QKV>
__global__ __launch_bounds__(256, 2) void gemm_f16(
        const uint32_t* __restrict__ Ah, const uint32_t* __restrict__ Al,
        const uint32_t* __restrict__ Bh,
        float* __restrict__ Cout,
        const float* __restrict__ cs, const float* __restrict__ sn, int K) {
    extern __shared__ uint32_t sm[];
    const int KPL = K >> 1;
    const int tid = threadIdx.x;
    const int warp = tid >> 5, lane = tid & 31;
    const int tg = lane >> 2, t4 = lane & 3;
    const int wm = (warp >> 2) * 64;
    const int wn = (warp & 3) * 32;
    const int bx = blockIdx.x, by = blockIdx.y;

    const int mrow = ((lane >> 3) & 1) * 8 + (lane & 7);
    const int mcol = (lane >> 4) * 4;
    int aoff[4], boff[2];
    #pragma unroll
    for (int i = 0; i < 4; i++) aoff[i] = (wm + 16 * i + mrow) * SG + mcol;
    #pragma unroll
    for (int jj = 0; jj < 2; jj++) boff[jj] = (wn + 16 * jj + mrow) * SG + mcol;

    const uint32_t* src[6];
    uint32_t dstoff[6];
    #pragma unroll
    for (int jj = 0; jj < 6; jj++) {
        int id = tid + 256 * jj;
        int arr = id >> 9, rem = id & 511;
        int row = rem >> 2, ch = rem & 3;
        const uint32_t* base =
            (arr == 0) ? Ah + (size_t)(by * 128 + row) * KPL :
            (arr == 1) ? Al + (size_t)(by * 128 + row) * KPL :
                         Bh + (size_t)(bx * 128 + row) * KPL;
        src[jj] = base + ch * 4;
        dstoff[jj] = arr * (128 * SG) + row * SG + ch * 4;
    }
    uint32_t sbase = (uint32_t)__cvta_generic_to_shared(sm);

    float acc[4][4][4];
    #pragma unroll
    for (int i = 0; i < 4; i++)
        #pragma unroll
        for (int j = 0; j < 4; j++)
            #pragma unroll
            for (int c = 0; c < 4; c++) acc[i][j][c] = 0.f;

    const int nk = K >> 5;

    #pragma unroll
    for (int jj = 0; jj < 6; jj++)
        cpa16(sbase + dstoff[jj] * 4, src[jj]);
    CP_COMMIT;

    for (int kc = 0; kc < nk; kc++) {
        int cur = kc & 1;
        if (kc + 1 < nk) {
            uint32_t bb = sbase + (cur ^ 1) * TBUF_B;
            int kadv = (kc + 1) * 16;
            #pragma unroll
            for (int jj = 0; jj < 6; jj++)
                cpa16(bb + dstoff[jj] * 4, src[jj] + kadv);
            CP_COMMIT;
            CP_WAIT1;
        } else {
            CP_WAIT0;
        }
        __syncthreads();

        uint32_t bb = sbase + cur * TBUF_B;
        #pragma unroll
        for (int s = 0; s < 2; s++) {
            uint32_t aH[4][4], aL[4][4];
            #pragma unroll
            for (int i = 0; i < 4; i++) {
                ldm4(aH[i], bb + (aoff[i] + 8 * s) * 4);
                ldm4(aL[i], bb + AREA_AL + (aoff[i] + 8 * s) * 4);
            }
            #pragma unroll
            for (int jj = 0; jj < 2; jj++) {
                uint32_t bh[4];
                ldm4(bh, bb + AREA_BH + (boff[jj] + 8 * s) * 4);
                #pragma unroll
                for (int i = 0; i < 4; i++) {
                    float* c0 = acc[i][2 * jj];
                    float* c1 = acc[i][2 * jj + 1];
                    mma_f16(c0, aH[i][0], aH[i][1], aH[i][2], aH[i][3], bh[0], bh[2]);
                    mma_f16(c0, aL[i][0], aL[i][1], aL[i][2], aL[i][3], bh[0], bh[2]);
                    mma_f16(c1, aH[i][0], aH[i][1], aH[i][2], aH[i][3], bh[1], bh[3]);
                    mma_f16(c1, aL[i][0], aL[i][1], aL[i][2], aL[i][3], bh[1], bh[3]);
                }
            }
        }
        __syncthreads();
    }

    // ---- epilogue (undo x64 weight scaling) ----
    const float INV = 1.f / 64.f;
    #pragma unroll
    for (int i = 0; i < 4; i++) {
        int r0 = by * 128 + wm + 16 * i + tg;
        #pragma unroll
        for (int j = 0; j < 4; j++) {
            int col = bx * 128 + wn + 8 * j + 2 * t4;
            float2 v0 = make_float2(acc[i][j][0] * INV, acc[i][j][1] * INV);
            float2 v1 = make_float2(acc[i][j][2] * INV, acc[i][j][3] * INV);
            if (QKV) {
                if (col < DIM) {
                    rope_split_store(g_Qh, g_Ql, KP, r0, col, v0, cs, sn);
                    rope_split_store(g_Qh, g_Ql, KP, r0 + 8, col, v1, cs, sn);
                } else if (col < DIM + KVDIM) {
                    int c2 = col - DIM;
                    rope_store_h(g_Kh, KVP, r0, c2, v0, cs, sn);
                    rope_store_h(g_Kh, KVP, r0 + 8, c2, v1, cs, sn);
                } else {
                    int c2 = col - DIM - KVDIM;
                    vt_store(r0, c2, v0);
                    vt_store(r0 + 8, c2, v1);
                }
            } else {
                *(float2*)(Cout + (size_t)r0 * DIM + col) = v0;
                *(float2*)(Cout + (size_t)(r0 + 8) * DIM + col) = v1;
            }
        }
    }
}

// ---------------- causal flash attention (fp16) ------------------------------
// S = (Qh+Ql)@Kh; O += Ph@Vh. 2 staged arrays (KH,VH): smem = 36,864 B.
// __launch_bounds__(256,2): cap 128 regs -> 2 CTAs/SM (reg-file was the limiter).
#define SAT   36
#define KVBUF (2 * 64 * SAT)

__global__ __launch_bounds__(256, 2) void attn_mma() {
    extern __shared__ uint32_t smu[];

    const int qt = (int)gridDim.x - 1 - (int)blockIdx.x;   // heavy tiles first
    const int h = blockIdx.y, b = blockIdx.z;
    const int kvh = h >> 2;
    const int tid = threadIdx.x;
    const int w = tid >> 5, lane = tid & 31;
    const int tg = lane >> 2, t4 = lane & 3;
    const int rA = w * 16 + tg, rB = rA + 8;
    const int rowAg = b * SEQ + qt * 128 + rA;
    const int rowBg = rowAg + 8;
    const int wrowmax = qt * 128 + w * 16 + 15;

    const int mrow = ((lane >> 3) & 1) * 8 + (lane & 7);
    const int mcol = (lane >> 4) * 4;
    int nfoff[4];
    #pragma unroll
    for (int jj = 0; jj < 4; jj++) nfoff[jj] = (16 * jj + mrow) * SAT + mcol;

    // cp.async: 2 base pointers, affine jj-offsets (reduced bookkeeping regs).
    // KH slots jj=0,1: rows row0, row0+32. VH slots jj=0,1: rows row0, row0+32.
    const int crow = tid >> 3, cch = tid & 7;            // 0..31 rows, 8 chunks
    const uint32_t* kbase = g_Kh + (size_t)(b * SEQ + crow) * KVP + kvh * 32 + cch * 4;
    const uint32_t* vbase = g_Vth + (size_t)((b * 8 + kvh) * HD + crow) * (SEQ / 2) + cch * 4;
    const uint32_t kdst = crow * SAT + cch * 4;
    const uint32_t vdst = (64 * SAT) + crow * SAT + cch * 4;
    uint32_t sbase = (uint32_t)__cvta_generic_to_shared(smu);

    uint32_t qH[4][4], qL[4][4];
    {
        const uint32_t* QA = g_Qh + (size_t)rowAg * KP + h * 32;
        const uint32_t* QB = g_Qh + (size_t)rowBg * KP + h * 32;
        const uint32_t* qA = g_Ql + (size_t)rowAg * KP + h * 32;
        const uint32_t* qB = g_Ql + (size_t)rowBg * KP + h * 32;
        #pragma unroll
        for (int s = 0; s < 4; s++) {
            qH[s][0] = QA[8 * s + t4];     qH[s][1] = QB[8 * s + t4];
            qH[s][2] = QA[8 * s + t4 + 4]; qH[s][3] = QB[8 * s + t4 + 4];
            qL[s][0] = qA[8 * s + t4];     qL[s][1] = qB[8 * s + t4];
            qL[s][2] = qA[8 * s + t4 + 4]; qL[s][3] = qB[8 * s + t4 + 4];
        }
    }

    float oacc[8][4];
    #pragma unroll
    for (int j = 0; j < 8; j++)
        #pragma unroll
        for (int c = 0; c < 4; c++) oacc[j][c] = 0.f;
    float mA = -1e30f, mB = -1e30f, lA = 0.f, lB = 0.f;
    const float SCL = 0.18033688011112042f;   // 0.125 * log2(e)

    const int nkb = 2 * qt + 2;

    // prologue: tile 0 into buffer 0
    #pragma unroll
    for (int jj = 0; jj < 2; jj++) {
        cpa16(sbase + (kdst + jj * 32 * SAT) * 4, kbase + (size_t)jj * 32 * KVP);
        cpa16(sbase + (vdst + jj * 32 * SAT) * 4, vbase + (size_t)jj * 32 * (SEQ / 2));
    }
    CP_COMMIT;

    for (int kb = 0; kb < nkb; kb++) {
        int cur = kb & 1;
        if (kb + 1 < nkb) {
            uint32_t boff = sbase + (cur ^ 1) * (KVBUF * 4);
            const uint32_t* kb2 = kbase + (size_t)(kb + 1) * 64 * KVP;
            const uint32_t* vb2 = vbase + (size_t)(kb + 1) * 32;
            #pragma unroll
            for (int jj = 0; jj < 2; jj++) {
                cpa16(boff + (kdst + jj * 32 * SAT) * 4, kb2 + (size_t)jj * 32 * KVP);
                cpa16(boff + (vdst + jj * 32 * SAT) * 4, vb2 + (size_t)jj * 32 * (SEQ / 2));
            }
            CP_COMMIT;
            CP_WAIT1;
        } else {
            CP_WAIT0;
        }
        __syncthreads();

        if (kb * 64 <= wrowmax) {
            uint32_t kvb = sbase + cur * (KVBUF * 4);
            const uint32_t VHo = 64 * SAT * 4;

            // ---- S = (Qh+Ql) @ Kh ----
            float sacc[8][4];
            #pragma unroll
            for (int j = 0; j < 8; j++)
                #pragma unroll
                for (int c = 0; c < 4; c++) sacc[j][c] = 0.f;
            #pragma unroll
            for (int s = 0; s < 4; s++) {
                #pragma unroll
                for (int jj = 0; jj < 4; jj++) {
                    uint32_t kh[4];
                    ldm4(kh, kvb + (nfoff[jj] + 8 * s) * 4);
                    float* c0 = sacc[2 * jj];
                    float* c1 = sacc[2 * jj + 1];
                    mma_f16(c0, qH[s][0], qH[s][1], qH[s][2], qH[s][3], kh[0], kh[2]);
                    mma_f16(c0, qL[s][0], qL[s][1], qL[s][2], qL[s][3], kh[0], kh[2]);
                    mma_f16(c1, qH[s][0], qH[s][1], qH[s][2], qH[s][3], kh[1], kh[3]);
                    mma_f16(c1, qL[s][0], qL[s][1], qL[s][2], qL[s][3], kh[1], kh[3]);
                }
            }
            // causal mask on raw scores (diagonal tiles)
            if (kb >= 2 * qt) {
                int rGA = qt * 128 + rA, rGB = rGA + 8;
                #pragma unroll
                for (int j = 0; j < 8; j++) {
                    int c0 = kb * 64 + 8 * j + 2 * t4;
                    if (c0 > rGA)     sacc[j][0] = -1e30f;
                    if (c0 + 1 > rGA) sacc[j][1] = -1e30f;
                    if (c0 > rGB)     sacc[j][2] = -1e30f;
                    if (c0 + 1 > rGB) sacc[j][3] = -1e30f;
                }
            }

            // ---- online softmax ----
            float mxA = -1e30f, mxB = -1e30f;
            #pragma unroll
            for (int j = 0; j < 8; j++) {
                mxA = fmaxf(mxA, fmaxf(sacc[j][0], sacc[j][1]));
                mxB = fmaxf(mxB, fmaxf(sacc[j][2], sacc[j][3]));
            }
            mxA = fmaxf(mxA, __shfl_xor_sync(0xffffffffu, mxA, 1));
            mxA = fmaxf(mxA, __shfl_xor_sync(0xffffffffu, mxA, 2));
            mxB = fmaxf(mxB, __shfl_xor_sync(0xffffffffu, mxB, 1));
            mxB = fmaxf(mxB, __shfl_xor_sync(0xffffffffu, mxB, 2));
            float nmA = fmaxf(mA, mxA * SCL), nmB = fmaxf(mB, mxB * SCL);
            float aA = ex2(mA - nmA), aB = ex2(mB - nmB);
            mA = nmA; mB = nmB;
            float sumA = 0.f, sumB = 0.f;
            uint32_t ph01[8], ph23[8];
            #pragma unroll
            for (int j = 0; j < 8; j++) {
                float p0 = ex2(fmaf(sacc[j][0], SCL, -nmA));
                float p1 = ex2(fmaf(sacc[j][1], SCL, -nmA));
                float p2 = ex2(fmaf(sacc[j][2], SCL, -nmB));
                float p3 = ex2(fmaf(sacc[j][3], SCL, -nmB));
                sumA += p0 + p1; sumB += p2 + p3;
                ph01[j] = pack_h(p0, p1);
                ph23[j] = pack_h(p2, p3);
            }
            lA = lA * aA + sumA;
            lB = lB * aB + sumB;
            #pragma unroll
            for (int j = 0; j < 8; j++) {
                oacc[j][0] *= aA; oacc[j][1] *= aA;
                oacc[j][2] *= aB; oacc[j][3] *= aB;
            }

            // ---- O += Ph @ Vh ----
            #pragma unroll
            for (int s = 0; s < 4; s++) {
                uint32_t aH0 = ph01[2 * s],     aH1 = ph23[2 * s];
                uint32_t aH2 = ph01[2 * s + 1], aH3 = ph23[2 * s + 1];
                #pragma unroll
                for (int jj = 0; jj < 4; jj++) {
                    uint32_t vh[4];
                    ldm4(vh, kvb + VHo + (nfoff[jj] + 8 * s) * 4);
                    mma_f16(oacc[2 * jj],     aH0, aH1, aH2, aH3, vh[0], vh[2]);
                    mma_f16(oacc[2 * jj + 1], aH0, aH1, aH2, aH3, vh[1], vh[3]);
                }
            }
        }
        __syncthreads();
    }

    // final cross-thread l reduction
    lA += __shfl_xor_sync(0xffffffffu, lA, 1);
    lA += __shfl_xor_sync(0xffffffffu, lA, 2);
    lB += __shfl_xor_sync(0xffffffffu, lB, 1);
    lB += __shfl_xor_sync(0xffffffffu, lB, 2);

    float ilA = 1.f / lA, ilB = 1.f / lB;
    #pragma unroll
    for (int j = 0; j < 8; j++) {
        uint32_t hh, ll;
        size_t oA = (size_t)rowAg * KP + h * 32 + 4 * j + t4;
        size_t oB = (size_t)rowBg * KP + h * 32 + 4 * j + t4;
        split_pack(oacc[j][0] * ilA, oacc[j][1] * ilA, hh, ll);
        g_Ah[oA] = hh; g_Al[oA] = ll;
        split_pack(oacc[j][2] * ilB, oacc[j][3] * ilB, hh, ll);
        g_Ah[oB] = hh; g_Al[oB] = ll;
    }
}

// ---------------- launch ----------------------------------------------------
extern "C" void kernel_launch(void* const* d_in, const int* in_sizes, int n_in,
                              void* d_out, int out_size) {
    const float* x  = (const float*)d_in[0];
    const float* fc = (const float*)d_in[1];
    const float* fs = (const float*)d_in[2];
    const float* wq = (const float*)d_in[3];
    const float* wk = (const float*)d_in[4];
    const float* wv = (const float*)d_in[5];
    const float* wo = (const float*)d_in[6];
    float* out = (float*)d_out;

    void *pxh, *pxl, *pwh, *pwoh, *pAh, *pAl;
    cudaGetSymbolAddress(&pxh, g_xh);   cudaGetSymbolAddress(&pxl, g_xl);
    cudaGetSymbolAddress(&pwh, g_wTh);
    cudaGetSymbolAddress(&pwoh, g_woTh);
    cudaGetSymbolAddress(&pAh, g_Ah);   cudaGetSymbolAddress(&pAl, g_Al);

    // ---- one-shot conversions ----
    conv_x<<<(ROWS * KP + 255) / 256, 256>>>(x, (uint32_t*)pxh, (uint32_t*)pxl, ROWS * KP);
    tconv_all<<<dim3(160, DIM / 64), 256>>>(wq, wk, wv, wo,
                                            (uint32_t*)pwh, (uint32_t*)pwoh);

    size_t gsmem = 2 * TBUF_B;   // 61440 B
    cudaFuncSetAttribute(gemm_f16<true>,  cudaFuncAttributeMaxDynamicSharedMemorySize, (int)gsmem);
    cudaFuncSetAttribute(gemm_f16<false>, cudaFuncAttributeMaxDynamicSharedMemorySize, (int)gsmem);

    // ---- fused QKV projection (epilogue: 1/64 + rope/split + V^T fp16) ----
    gemm_f16<true><<<dim3(NW / 128, ROWS / 128), 256, gsmem>>>(
        (uint32_t*)pxh, (uint32_t*)pxl, (uint32_t*)pwh,
        nullptr, fc, fs, DIM);

    // ---- attention ----
    {
        size_t smem = 2 * KVBUF * sizeof(uint32_t);  // 36864 B
        cudaFuncSetAttribute(attn_mma, cudaFuncAttributeMaxDynamicSharedMemorySize, (int)smem);
        attn_mma<<<dim3(SEQ / 128, N_HEADS, BSZ), 256, smem>>>();
    }

    // ---- output projection ----
    gemm_f16<false><<<dim3(DIM / 128, ROWS / 128), 256, gsmem>>>(
        (uint32_t*)pAh, (uint32_t*)pAl, (uint32_t*)pwoh,
        out, nullptr, nullptr, DIM);
}

// round 16
// speedup vs baseline: 2.2836x; 1.5104x over previous
#include <cuda_runtime.h>
#include <cuda_fp16.h>
#include <cstdint>

#define BSZ      2
#define SEQ      2048
#define DIM      2048
#define N_HEADS  32
#define N_KVH    8
#define HD       64
#define ROWS     (BSZ*SEQ)          // 4096
#define KVDIM    (N_KVH*HD)         // 512
#define KP       (DIM/2)            // 1024 u32 pairs per DIM row
#define KVP      (KVDIM/2)          // 256
#define NW       (DIM + 2*KVDIM)    // 3072 fused qkv width

// ---------------- scratch (device globals; no allocations allowed) ----------
__device__ __align__(256) uint32_t g_xh [ROWS * KP];                      // x fp16 hi
__device__ __align__(256) uint32_t g_wTh[NW * KP];                        // W^T fp16 hi (x64)
__device__ __align__(256) uint32_t g_woTh[DIM * KP];                      // Wo^T fp16 hi (x64)
__device__ __align__(256) uint32_t g_Qh[ROWS * KP],   g_Ql[ROWS * KP];    // Q fp16 hi/lo (roped)
__device__ __align__(256) uint32_t g_Kh[ROWS * KVP];                      // K fp16 hi (roped)
__device__ __align__(256) uint32_t g_Vth[BSZ*N_KVH*HD*(SEQ/2)];           // V^T fp16 hi
__device__ __align__(256) uint32_t g_Ah[ROWS * KP];                       // attn out fp16 hi

// ---------------- helpers ----------------------------------------------------
__device__ __forceinline__ void split_pack(float x, float y, uint32_t& hv, uint32_t& lv) {
    __half2 hb = __floats2half2_rn(x, y);
    hv = *reinterpret_cast<uint32_t*>(&hb);
    float rx = x - __half2float(__low2half(hb));
    float ry = y - __half2float(__high2half(hb));
    __half2 lb = __floats2half2_rn(rx, ry);
    lv = *reinterpret_cast<uint32_t*>(&lb);
}

__device__ __forceinline__ uint32_t pack_h(float x, float y) {
    __half2 hb = __floats2half2_rn(x, y);
    return *reinterpret_cast<uint32_t*>(&hb);
}

__device__ __forceinline__ void mma_f16(float* c,
        uint32_t a0, uint32_t a1, uint32_t a2, uint32_t a3,
        uint32_t b0, uint32_t b1) {
    asm volatile(
        "mma.sync.aligned.m16n8k16.row.col.f32.f16.f16.f32 "
        "{%0,%1,%2,%3}, {%4,%5,%6,%7}, {%8,%9}, {%0,%1,%2,%3};"
        : "+f"(c[0]), "+f"(c[1]), "+f"(c[2]), "+f"(c[3])
        : "r"(a0), "r"(a1), "r"(a2), "r"(a3), "r"(b0), "r"(b1));
}

__device__ __forceinline__ void ldm4(uint32_t* r, uint32_t addr) {
    asm volatile("ldmatrix.sync.aligned.m8n8.x4.shared.b16 {%0,%1,%2,%3}, [%4];"
                 : "=r"(r[0]), "=r"(r[1]), "=r"(r[2]), "=r"(r[3]) : "r"(addr));
}

__device__ __forceinline__ float ex2(float x) {
    float y;
    asm("ex2.approx.ftz.f32 %0, %1;" : "=f"(y) : "f"(x));
    return y;
}

__device__ __forceinline__ void cpa16(uint32_t dst_smem, const void* src) {
    asm volatile("cp.async.cg.shared.global [%0], [%1], 16;\n"
                 :: "r"(dst_smem), "l"(src));
}
#define CP_COMMIT asm volatile("cp.async.commit_group;\n" ::)
#define CP_WAIT0  asm volatile("cp.async.wait_group 0;\n" ::)
#define CP_WAIT1  asm volatile("cp.async.wait_group 1;\n" ::)

// rope + fp16 split store of a (even,odd) column pair
__device__ __forceinline__ void rope_split_store(
        uint32_t* __restrict__ dh, uint32_t* __restrict__ dl, int ldp,
        int row, int col, float2 v,
        const float* __restrict__ cs, const float* __restrict__ sn) {
    int s = row & (SEQ - 1);
    int p = (col & 63) >> 1;
    float c = cs[s * 32 + p], si = sn[s * 32 + p];
    float orr = v.x * c - v.y * si;
    float oi  = v.x * si + v.y * c;
    uint32_t h, l;
    split_pack(orr, oi, h, l);
    size_t o = (size_t)row * ldp + (col >> 1);
    dh[o] = h; dl[o] = l;
}

// rope + fp16 hi-only store (K)
__device__ __forceinline__ void rope_store_h(
        uint32_t* __restrict__ dh, int ldp,
        int row, int col, float2 v,
        const float* __restrict__ cs, const float* __restrict__ sn) {
    int s = row & (SEQ - 1);
    int p = (col & 63) >> 1;
    float c = cs[s * 32 + p], si = sn[s * 32 + p];
    dh[(size_t)row * ldp + (col >> 1)] =
        pack_h(v.x * c - v.y * si, v.x * si + v.y * c);
}

// V^T fp16 store: thread holds (d, d+1) of one sequence row; scatter 16-bit
__device__ __forceinline__ void vt_store(int row, int c2, float2 v) {
    int kvh = c2 >> 6, d = c2 & 63;
    int b = row >> 11, s = row & (SEQ - 1);
    int bz = b * 8 + kvh;
    uint16_t* vt = (uint16_t*)g_Vth;
    size_t base = ((size_t)(bz * HD + d) * (SEQ / 2) + (s >> 1)) * 2 + (s & 1);
    __half hx = __float2half_rn(v.x), hy = __float2half_rn(v.y);
    vt[base]       = *reinterpret_cast<uint16_t*>(&hx);
    vt[base + SEQ] = *reinterpret_cast<uint16_t*>(&hy);   // d+1 row of V^T
}

// ---------------- conversion kernels ----------------------------------------
__global__ void conv_x(const float* __restrict__ x,
                       uint32_t* __restrict__ xh, int npairs) {
    int i = blockIdx.x * blockDim.x + threadIdx.x;
    if (i >= npairs) return;
    float2 v = *(const float2*)(x + 2 * (size_t)i);
    xh[i] = pack_h(v.x, v.y);
}

// weight transposes: fp16 hi only, pre-scaled x64 (epilogue multiplies 1/64)
__global__ __launch_bounds__(256) void tconv_all(
        const float* __restrict__ wq, const float* __restrict__ wk,
        const float* __restrict__ wv, const float* __restrict__ wo,
        uint32_t* __restrict__ Th, uint32_t* __restrict__ Oh) {
    __shared__ float s[64][33];
    const int tid = threadIdx.x;
    const int bx = blockIdx.x, k0 = blockIdx.y * 64;
    const float* W; int N, rowoff, nb;
    uint32_t* Dh;
    if (bx < 64)       { W = wq; N = DIM;   rowoff = 0;           nb = bx;      Dh = Th; }
    else if (bx < 80)  { W = wk; N = KVDIM; rowoff = DIM;         nb = bx - 64; Dh = Th; }
    else if (bx < 96)  { W = wv; N = KVDIM; rowoff = DIM + KVDIM; nb = bx - 80; Dh = Th; }
    else               { W = wo; N = DIM;   rowoff = 0;           nb = bx - 96; Dh = Oh; }
    const int n0 = nb * 32;
    #pragma unroll
    for (int jj = 0; jj < 8; jj++) {
        int id = tid + 256 * jj;
        int k = id >> 5, n = id & 31;
        s[k][n] = W[(size_t)(k0 + k) * N + n0 + n];
    }
    __syncthreads();
    #pragma unroll
    for (int jj = 0; jj < 4; jj++) {
        int id = tid + 256 * jj;
        int n = id >> 5, kp = id & 31;
        size_t o = (size_t)(rowoff + n0 + n) * KP + (k0 >> 1) + kp;
        Dh[o] = pack_h(s[2 * kp][n] * 64.f, s[2 * kp + 1][n] * 64.f);
    }
}

// ---------------- fp16 GEMM (single mma: Ah @ Bh) ---------------------------
// 128x128 tile, BK=32, 256 threads; 2 staged arrays (AH|BH) = 40 KB smem.
#define SG        20
#define TBUF_U32  (2 * 128 * SG)
#define TBUF_B    (TBUF_U32 * 4)        // 20480 bytes per stage
#define AREA_BH   (128 * SG * 4)

template <bool QKV>
__global__ __launch_bounds__(256, 2) void gemm_f16(
        const uint32_t* __restrict__ Ah, const uint32_t* __restrict__ Bh,
        float* __restrict__ Cout,
        const float* __restrict__ cs, const float* __restrict__ sn, int K) {
    extern __shared__ uint32_t sm[];
    const int KPL = K >> 1;
    const int tid = threadIdx.x;
    const int warp = tid >> 5, lane = tid & 31;
    const int tg = lane >> 2, t4 = lane & 3;
    const int wm = (warp >> 2) * 64;
    const int wn = (warp & 3) * 32;
    const int bx = blockIdx.x, by = blockIdx.y;

    const int mrow = ((lane >> 3) & 1) * 8 + (lane & 7);
    const int mcol = (lane >> 4) * 4;
    int aoff[4], boff[2];
    #pragma unroll
    for (int i = 0; i < 4; i++) aoff[i] = (wm + 16 * i + mrow) * SG + mcol;
    #pragma unroll
    for (int jj = 0; jj < 2; jj++) boff[jj] = (wn + 16 * jj + mrow) * SG + mcol;

    const uint32_t* src[4];
    uint32_t dstoff[4];
    #pragma unroll
    for (int jj = 0; jj < 4; jj++) {
        int id = tid + 256 * jj;
        int arr = id >> 9, rem = id & 511;
        int row = rem >> 2, ch = rem & 3;
        const uint32_t* base =
            (arr == 0) ? Ah + (size_t)(by * 128 + row) * KPL :
                         Bh + (size_t)(bx * 128 + row) * KPL;
        src[jj] = base + ch * 4;
        dstoff[jj] = arr * (128 * SG) + row * SG + ch * 4;
    }
    uint32_t sbase = (uint32_t)__cvta_generic_to_shared(sm);

    float acc[4][4][4];
    #pragma unroll
    for (int i = 0; i < 4; i++)
        #pragma unroll
        for (int j = 0; j < 4; j++)
            #pragma unroll
            for (int c = 0; c < 4; c++) acc[i][j][c] = 0.f;

    const int nk = K >> 5;

    #pragma unroll
    for (int jj = 0; jj < 4; jj++)
        cpa16(sbase + dstoff[jj] * 4, src[jj]);
    CP_COMMIT;

    for (int kc = 0; kc < nk; kc++) {
        int cur = kc & 1;
        if (kc + 1 < nk) {
            uint32_t bb = sbase + (cur ^ 1) * TBUF_B;
            int kadv = (kc + 1) * 16;
            #pragma unroll
            for (int jj = 0; jj < 4; jj++)
                cpa16(bb + dstoff[jj] * 4, src[jj] + kadv);
            CP_COMMIT;
            CP_WAIT1;
        } else {
            CP_WAIT0;
        }
        __syncthreads();

        uint32_t bb = sbase + cur * TBUF_B;
        #pragma unroll
        for (int s = 0; s < 2; s++) {
            uint32_t aH[4][4];
            #pragma unroll
            for (int i = 0; i < 4; i++)
                ldm4(aH[i], bb + (aoff[i] + 8 * s) * 4);
            #pragma unroll
            for (int jj = 0; jj < 2; jj++) {
                uint32_t bh[4];
                ldm4(bh, bb + AREA_BH + (boff[jj] + 8 * s) * 4);
                #pragma unroll
                for (int i = 0; i < 4; i++) {
                    mma_f16(acc[i][2 * jj],     aH[i][0], aH[i][1], aH[i][2], aH[i][3], bh[0], bh[2]);
                    mma_f16(acc[i][2 * jj + 1], aH[i][0], aH[i][1], aH[i][2], aH[i][3], bh[1], bh[3]);
                }
            }
        }
        __syncthreads();
    }

    // ---- epilogue (undo x64 weight scaling) ----
    const float INV = 1.f / 64.f;
    #pragma unroll
    for (int i = 0; i < 4; i++) {
        int r0 = by * 128 + wm + 16 * i + tg;
        #pragma unroll
        for (int j = 0; j < 4; j++) {
            int col = bx * 128 + wn + 8 * j + 2 * t4;
            float2 v0 = make_float2(acc[i][j][0] * INV, acc[i][j][1] * INV);
            float2 v1 = make_float2(acc[i][j][2] * INV, acc[i][j][3] * INV);
            if (QKV) {
                if (col < DIM) {
                    rope_split_store(g_Qh, g_Ql, KP, r0, col, v0, cs, sn);
                    rope_split_store(g_Qh, g_Ql, KP, r0 + 8, col, v1, cs, sn);
                } else if (col < DIM + KVDIM) {
                    int c2 = col - DIM;
                    rope_store_h(g_Kh, KVP, r0, c2, v0, cs, sn);
                    rope_store_h(g_Kh, KVP, r0 + 8, c2, v1, cs, sn);
                } else {
                    int c2 = col - DIM - KVDIM;
                    vt_store(r0, c2, v0);
                    vt_store(r0 + 8, c2, v1);
                }
            } else {
                *(float2*)(Cout + (size_t)r0 * DIM + col) = v0;
                *(float2*)(Cout + (size_t)(r0 + 8) * DIM + col) = v1;
            }
        }
    }
}

// ---------------- causal flash attention (fp16) ------------------------------
// S = (Qh+Ql)@Kh; O += Ph@Vh. 2 staged arrays (KH,VH): smem = 36,864 B.
#define SAT   36
#define KVBUF (2 * 64 * SAT)

__global__ __launch_bounds__(256, 2) void attn_mma() {
    extern __shared__ uint32_t smu[];

    const int qt = (int)gridDim.x - 1 - (int)blockIdx.x;   // heavy tiles first
    const int h = blockIdx.y, b = blockIdx.z;
    const int kvh = h >> 2;
    const int tid = threadIdx.x;
    const int w = tid >> 5, lane = tid & 31;
    const int tg = lane >> 2, t4 = lane & 3;
    const int rA = w * 16 + tg, rB = rA + 8;
    const int rowAg = b * SEQ + qt * 128 + rA;
    const int rowBg = rowAg + 8;
    const int wrowmax = qt * 128 + w * 16 + 15;

    const int mrow = ((lane >> 3) & 1) * 8 + (lane & 7);
    const int mcol = (lane >> 4) * 4;
    int nfoff[4];
    #pragma unroll
    for (int jj = 0; jj < 4; jj++) nfoff[jj] = (16 * jj + mrow) * SAT + mcol;

    const int crow = tid >> 3, cch = tid & 7;
    const uint32_t* kbase = g_Kh + (size_t)(b * SEQ + crow) * KVP + kvh * 32 + cch * 4;
    const uint32_t* vbase = g_Vth + (size_t)((b * 8 + kvh) * HD + crow) * (SEQ / 2) + cch * 4;
    const uint32_t kdst = crow * SAT + cch * 4;
    const uint32_t vdst = (64 * SAT) + crow * SAT + cch * 4;
    uint32_t sbase = (uint32_t)__cvta_generic_to_shared(smu);

    uint32_t qH[4][4], qL[4][4];
    {
        const uint32_t* QA = g_Qh + (size_t)rowAg * KP + h * 32;
        const uint32_t* QB = g_Qh + (size_t)rowBg * KP + h * 32;
        const uint32_t* qA = g_Ql + (size_t)rowAg * KP + h * 32;
        const uint32_t* qB = g_Ql + (size_t)rowBg * KP + h * 32;
        #pragma unroll
        for (int s = 0; s < 4; s++) {
            qH[s][0] = QA[8 * s + t4];     qH[s][1] = QB[8 * s + t4];
            qH[s][2] = QA[8 * s + t4 + 4]; qH[s][3] = QB[8 * s + t4 + 4];
            qL[s][0] = qA[8 * s + t4];     qL[s][1] = qB[8 * s + t4];
            qL[s][2] = qA[8 * s + t4 + 4]; qL[s][3] = qB[8 * s + t4 + 4];
        }
    }

    float oacc[8][4];
    #pragma unroll
    for (int j = 0; j < 8; j++)
        #pragma unroll
        for (int c = 0; c < 4; c++) oacc[j][c] = 0.f;
    float mA = -1e30f, mB = -1e30f, lA = 0.f, lB = 0.f;
    const float SCL = 0.18033688011112042f;   // 0.125 * log2(e)

    const int nkb = 2 * qt + 2;

    #pragma unroll
    for (int jj = 0; jj < 2; jj++) {
        cpa16(sbase + (kdst + jj * 32 * SAT) * 4, kbase + (size_t)jj * 32 * KVP);
        cpa16(sbase + (vdst + jj * 32 * SAT) * 4, vbase + (size_t)jj * 32 * (SEQ / 2));
    }
    CP_COMMIT;

    for (int kb = 0; kb < nkb; kb++) {
        int cur = kb & 1;
        if (kb + 1 < nkb) {
            uint32_t boff = sbase + (cur ^ 1) * (KVBUF * 4);
            const uint32_t* kb2 = kbase + (size_t)(kb + 1) * 64 * KVP;
            const uint32_t* vb2 = vbase + (size_t)(kb + 1) * 32;
            #pragma unroll
            for (int jj = 0; jj < 2; jj++) {
                cpa16(boff + (kdst + jj * 32 * SAT) * 4, kb2 + (size_t)jj * 32 * KVP);
                cpa16(boff + (vdst + jj * 32 * SAT) * 4, vb2 + (size_t)jj * 32 * (SEQ / 2));
            }
            CP_COMMIT;
            CP_WAIT1;
        } else {
            CP_WAIT0;
        }
        __syncthreads();

        if (kb * 64 <= wrowmax) {
            uint32_t kvb = sbase + cur * (KVBUF * 4);
            const uint32_t VHo = 64 * SAT * 4;

            // ---- S = (Qh+Ql) @ Kh ----
            float sacc[8][4];
            #pragma unroll
            for (int j = 0; j < 8; j++)
                #pragma unroll
                for (int c = 0; c < 4; c++) sacc[j][c] = 0.f;
            #pragma unroll
            for (int s = 0; s < 4; s++) {
                #pragma unroll
                for (int jj = 0; jj < 4; jj++) {
                    uint32_t kh[4];
                    ldm4(kh, kvb + (nfoff[jj] + 8 * s) * 4);
                    float* c0 = sacc[2 * jj];
                    float* c1 = sacc[2 * jj + 1];
                    mma_f16(c0, qH[s][0], qH[s][1], qH[s][2], qH[s][3], kh[0], kh[2]);
                    mma_f16(c0, qL[s][0], qL[s][1], qL[s][2], qL[s][3], kh[0], kh[2]);
                    mma_f16(c1, qH[s][0], qH[s][1], qH[s][2], qH[s][3], kh[1], kh[3]);
                    mma_f16(c1, qL[s][0], qL[s][1], qL[s][2], qL[s][3], kh[1], kh[3]);
                }
            }
            // causal mask on raw scores (diagonal tiles)
            if (kb >= 2 * qt) {
                int rGA = qt * 128 + rA, rGB = rGA + 8;
                #pragma unroll
                for (int j = 0; j < 8; j++) {
                    int c0 = kb * 64 + 8 * j + 2 * t4;
                    if (c0 > rGA)     sacc[j][0] = -1e30f;
                    if (c0 + 1 > rGA) sacc[j][1] = -1e30f;
                    if (c0 > rGB)     sacc[j][2] = -1e30f;
                    if (c0 + 1 > rGB) sacc[j][3] = -1e30f;
                }
            }

            // ---- online softmax ----
            float mxA = -1e30f, mxB = -1e30f;
            #pragma unroll
            for (int j = 0; j < 8; j++) {
                mxA = fmaxf(mxA, fmaxf(sacc[j][0], sacc[j][1]));
                mxB = fmaxf(mxB, fmaxf(sacc[j][2], sacc[j][3]));
            }
            mxA = fmaxf(mxA, __shfl_xor_sync(0xffffffffu, mxA, 1));
            mxA = fmaxf(mxA, __shfl_xor_sync(0xffffffffu, mxA, 2));
            mxB = fmaxf(mxB, __shfl_xor_sync(0xffffffffu, mxB, 1));
            mxB = fmaxf(mxB, __shfl_xor_sync(0xffffffffu, mxB, 2));
            float nmA = fmaxf(mA, mxA * SCL), nmB = fmaxf(mB, mxB * SCL);
            float aA = ex2(mA - nmA), aB = ex2(mB - nmB);
            mA = nmA; mB = nmB;
            float sumA = 0.f, sumB = 0.f;
            uint32_t ph01[8], ph23[8];
            #pragma unroll
            for (int j = 0; j < 8; j++) {
                float p0 = ex2(fmaf(sacc[j][0], SCL, -nmA));
                float p1 = ex2(fmaf(sacc[j][1], SCL, -nmA));
                float p2 = ex2(fmaf(sacc[j][2], SCL, -nmB));
                float p3 = ex2(fmaf(sacc[j][3], SCL, -nmB));
                sumA += p0 + p1; sumB += p2 + p3;
                ph01[j] = pack_h(p0, p1);
                ph23[j] = pack_h(p2, p3);
            }
            lA = lA * aA + sumA;
            lB = lB * aB + sumB;
            #pragma unroll
            for (int j = 0; j < 8; j++) {
                oacc[j][0] *= aA; oacc[j][1] *= aA;
                oacc[j][2] *= aB; oacc[j][3] *= aB;
            }

            // ---- O += Ph @ Vh ----
            #pragma unroll
            for (int s = 0; s < 4; s++) {
                uint32_t aH0 = ph01[2 * s],     aH1 = ph23[2 * s];
                uint32_t aH2 = ph01[2 * s + 1], aH3 = ph23[2 * s + 1];
                #pragma unroll
                for (int jj = 0; jj < 4; jj++) {
                    uint32_t vh[4];
                    ldm4(vh, kvb + VHo + (nfoff[jj] + 8 * s) * 4);
                    mma_f16(oacc[2 * jj],     aH0, aH1, aH2, aH3, vh[0], vh[2]);
                    mma_f16(oacc[2 * jj + 1], aH0, aH1, aH2, aH3, vh[1], vh[3]);
                }
            }
        }
        __syncthreads();
    }

    // final cross-thread l reduction
    lA += __shfl_xor_sync(0xffffffffu, lA, 1);
    lA += __shfl_xor_sync(0xffffffffu, lA, 2);
    lB += __shfl_xor_sync(0xffffffffu, lB, 1);
    lB += __shfl_xor_sync(0xffffffffu, lB, 2);

    float ilA = 1.f / lA, ilB = 1.f / lB;
    #pragma unroll
    for (int j = 0; j < 8; j++) {
        size_t oA = (size_t)rowAg * KP + h * 32 + 4 * j + t4;
        size_t oB = (size_t)rowBg * KP + h * 32 + 4 * j + t4;
        g_Ah[oA] = pack_h(oacc[j][0] * ilA, oacc[j][1] * ilA);
        g_Ah[oB] = pack_h(oacc[j][2] * ilB, oacc[j][3] * ilB);
    }
}

// ---------------- launch ----------------------------------------------------
extern "C" void kernel_launch(void* const* d_in, const int* in_sizes, int n_in,
                              void* d_out, int out_size) {
    const float* x  = (const float*)d_in[0];
    const float* fc = (const float*)d_in[1];
    const float* fs = (const float*)d_in[2];
    const float* wq = (const float*)d_in[3];
    const float* wk = (const float*)d_in[4];
    const float* wv = (const float*)d_in[5];
    const float* wo = (const float*)d_in[6];
    float* out = (float*)d_out;

    void *pxh, *pwh, *pwoh, *pAh;
    cudaGetSymbolAddress(&pxh, g_xh);
    cudaGetSymbolAddress(&pwh, g_wTh);
    cudaGetSymbolAddress(&pwoh, g_woTh);
    cudaGetSymbolAddress(&pAh, g_Ah);

    // ---- one-shot conversions ----
    conv_x<<<(ROWS * KP + 255) / 256, 256>>>(x, (uint32_t*)pxh, ROWS * KP);
    tconv_all<<<dim3(160, DIM / 64), 256>>>(wq, wk, wv, wo,
                                            (uint32_t*)pwh, (uint32_t*)pwoh);

    size_t gsmem = 2 * TBUF_B;   // 40960 B
    cudaFuncSetAttribute(gemm_f16<true>,  cudaFuncAttributeMaxDynamicSharedMemorySize, (int)gsmem);
    cudaFuncSetAttribute(gemm_f16<false>, cudaFuncAttributeMaxDynamicSharedMemorySize, (int)gsmem);

    // ---- fused QKV projection (epilogue: 1/64 + rope/split + V^T fp16) ----
    gemm_f16<true><<<dim3(NW / 128, ROWS / 128), 256, gsmem>>>(
        (uint32_t*)pxh, (uint32_t*)pwh, nullptr, fc, fs, DIM);

    // ---- attention ----
    {
        size_t smem = 2 * KVBUF * sizeof(uint32_t);  // 36864 B
        cudaFuncSetAttribute(attn_mma, cudaFuncAttributeMaxDynamicSharedMemorySize, (int)smem);
        attn_mma<<<dim3(SEQ / 128, N_HEADS, BSZ), 256, smem>>>();
    }

    // ---- output projection ----
    gemm_f16<false><<<dim3(DIM / 128, ROWS / 128), 256, gsmem>>>(
        (uint32_t*)pAh, (uint32_t*)pwoh, out, nullptr, nullptr, DIM);
}

// round 17
// speedup vs baseline: 2.4640x; 1.0790x over previous
#include <cuda_runtime.h>
#include <cuda_fp16.h>
#include <cstdint>

#define BSZ      2
#define SEQ      2048
#define DIM      2048
#define N_HEADS  32
#define N_KVH    8
#define HD       64
#define ROWS     (BSZ*SEQ)          // 4096
#define KVDIM    (N_KVH*HD)         // 512
#define KP       (DIM/2)            // 1024 u32 pairs per DIM row
#define KVP      (KVDIM/2)          // 256
#define NW       (DIM + 2*KVDIM)    // 3072 fused qkv width

// ---------------- scratch (device globals; no allocations allowed) ----------
__device__ __align__(256) uint32_t g_xh [ROWS * KP];                      // x fp16 hi
__device__ __align__(256) uint32_t g_wTh[NW * KP];                        // W^T fp16 hi (x64)
__device__ __align__(256) uint32_t g_woTh[DIM * KP];                      // Wo^T fp16 hi (x64)
__device__ __align__(256) uint32_t g_Qh[ROWS * KP];                       // Q fp16 hi (roped)
__device__ __align__(256) uint32_t g_Kh[ROWS * KVP];                      // K fp16 hi (roped)
__device__ __align__(256) uint32_t g_Vth[BSZ*N_KVH*HD*(SEQ/2)];           // V^T fp16 hi
__device__ __align__(256) uint32_t g_Ah[ROWS * KP];                       // attn out fp16 hi

// ---------------- helpers ----------------------------------------------------
__device__ __forceinline__ uint32_t pack_h(float x, float y) {
    __half2 hb = __floats2half2_rn(x, y);
    return *reinterpret_cast<uint32_t*>(&hb);
}

__device__ __forceinline__ void mma_f16(float* c,
        uint32_t a0, uint32_t a1, uint32_t a2, uint32_t a3,
        uint32_t b0, uint32_t b1) {
    asm volatile(
        "mma.sync.aligned.m16n8k16.row.col.f32.f16.f16.f32 "
        "{%0,%1,%2,%3}, {%4,%5,%6,%7}, {%8,%9}, {%0,%1,%2,%3};"
        : "+f"(c[0]), "+f"(c[1]), "+f"(c[2]), "+f"(c[3])
        : "r"(a0), "r"(a1), "r"(a2), "r"(a3), "r"(b0), "r"(b1));
}

__device__ __forceinline__ void ldm4(uint32_t* r, uint32_t addr) {
    asm volatile("ldmatrix.sync.aligned.m8n8.x4.shared.b16 {%0,%1,%2,%3}, [%4];"
                 : "=r"(r[0]), "=r"(r[1]), "=r"(r[2]), "=r"(r[3]) : "r"(addr));
}

__device__ __forceinline__ float ex2(float x) {
    float y;
    asm("ex2.approx.ftz.f32 %0, %1;" : "=f"(y) : "f"(x));
    return y;
}

__device__ __forceinline__ void cpa16(uint32_t dst_smem, const void* src) {
    asm volatile("cp.async.cg.shared.global [%0], [%1], 16;\n"
                 :: "r"(dst_smem), "l"(src));
}
#define CP_COMMIT asm volatile("cp.async.commit_group;\n" ::)
#define CP_WAIT0  asm volatile("cp.async.wait_group 0;\n" ::)
#define CP_WAIT1  asm volatile("cp.async.wait_group 1;\n" ::)

// rope + fp16 hi-only store (Q and K)
__device__ __forceinline__ void rope_store_h(
        uint32_t* __restrict__ dh, int ldp,
        int row, int col, float2 v,
        const float* __restrict__ cs, const float* __restrict__ sn) {
    int s = row & (SEQ - 1);
    int p = (col & 63) >> 1;
    float c = cs[s * 32 + p], si = sn[s * 32 + p];
    dh[(size_t)row * ldp + (col >> 1)] =
        pack_h(v.x * c - v.y * si, v.x * si + v.y * c);
}

// V^T fp16 store: thread holds (d, d+1) of one sequence row; scatter 16-bit
__device__ __forceinline__ void vt_store(int row, int c2, float2 v) {
    int kvh = c2 >> 6, d = c2 & 63;
    int b = row >> 11, s = row & (SEQ - 1);
    int bz = b * 8 + kvh;
    uint16_t* vt = (uint16_t*)g_Vth;
    size_t base = ((size_t)(bz * HD + d) * (SEQ / 2) + (s >> 1)) * 2 + (s & 1);
    __half hx = __float2half_rn(v.x), hy = __float2half_rn(v.y);
    vt[base]       = *reinterpret_cast<uint16_t*>(&hx);
    vt[base + SEQ] = *reinterpret_cast<uint16_t*>(&hy);   // d+1 row of V^T
}

// ---------------- conversion kernels ----------------------------------------
__global__ void conv_x(const float* __restrict__ x,
                       uint32_t* __restrict__ xh, int npairs) {
    int i = blockIdx.x * blockDim.x + threadIdx.x;
    if (i >= npairs) return;
    float2 v = *(const float2*)(x + 2 * (size_t)i);
    xh[i] = pack_h(v.x, v.y);
}

// weight transposes: fp16 hi only, pre-scaled x64 (epilogue multiplies 1/64)
__global__ __launch_bounds__(256) void tconv_all(
        const float* __restrict__ wq, const float* __restrict__ wk,
        const float* __restrict__ wv, const float* __restrict__ wo,
        uint32_t* __restrict__ Th, uint32_t* __restrict__ Oh) {
    __shared__ float s[64][33];
    const int tid = threadIdx.x;
    const int bx = blockIdx.x, k0 = blockIdx.y * 64;
    const float* W; int N, rowoff, nb;
    uint32_t* Dh;
    if (bx < 64)       { W = wq; N = DIM;   rowoff = 0;           nb = bx;      Dh = Th; }
    else if (bx < 80)  { W = wk; N = KVDIM; rowoff = DIM;         nb = bx - 64; Dh = Th; }
    else if (bx < 96)  { W = wv; N = KVDIM; rowoff = DIM + KVDIM; nb = bx - 80; Dh = Th; }
    else               { W = wo; N = DIM;   rowoff = 0;           nb = bx - 96; Dh = Oh; }
    const int n0 = nb * 32;
    #pragma unroll
    for (int jj = 0; jj < 8; jj++) {
        int id = tid + 256 * jj;
        int k = id >> 5, n = id & 31;
        s[k][n] = W[(size_t)(k0 + k) * N + n0 + n];
    }
    __syncthreads();
    #pragma unroll
    for (int jj = 0; jj < 4; jj++) {
        int id = tid + 256 * jj;
        int n = id >> 5, kp = id & 31;
        size_t o = (size_t)(rowoff + n0 + n) * KP + (k0 >> 1) + kp;
        Dh[o] = pack_h(s[2 * kp][n] * 64.f, s[2 * kp + 1][n] * 64.f);
    }
}

// ---------------- fp16 GEMM (single mma: Ah @ Bh) ---------------------------
// 128x128 tile, BK=32, 256 threads; 2 staged arrays (AH|BH) = 40 KB smem.
#define SG        20
#define TBUF_U32  (2 * 128 * SG)
#define TBUF_B    (TBUF_U32 * 4)        // 20480 bytes per stage
#define AREA_BH   (128 * SG * 4)

template <bool QKV>
__global__ __launch_bounds__(256, 2) void gemm_f16(
        const uint32_t* __restrict__ Ah, const uint32_t* __restrict__ Bh,
        float* __restrict__ Cout,
        const float* __restrict__ cs, const float* __restrict__ sn, int K) {
    extern __shared__ uint32_t sm[];
    const int KPL = K >> 1;
    const int tid = threadIdx.x;
    const int warp = tid >> 5, lane = tid & 31;
    const int tg = lane >> 2, t4 = lane & 3;
    const int wm = (warp >> 2) * 64;
    const int wn = (warp & 3) * 32;
    const int bx = blockIdx.x, by = blockIdx.y;

    const int mrow = ((lane >> 3) & 1) * 8 + (lane & 7);
    const int mcol = (lane >> 4) * 4;
    int aoff[4], boff[2];
    #pragma unroll
    for (int i = 0; i < 4; i++) aoff[i] = (wm + 16 * i + mrow) * SG + mcol;
    #pragma unroll
    for (int jj = 0; jj < 2; jj++) boff[jj] = (wn + 16 * jj + mrow) * SG + mcol;

    const uint32_t* src[4];
    uint32_t dstoff[4];
    #pragma unroll
    for (int jj = 0; jj < 4; jj++) {
        int id = tid + 256 * jj;
        int arr = id >> 9, rem = id & 511;
        int row = rem >> 2, ch = rem & 3;
        const uint32_t* base =
            (arr == 0) ? Ah + (size_t)(by * 128 + row) * KPL :
                         Bh + (size_t)(bx * 128 + row) * KPL;
        src[jj] = base + ch * 4;
        dstoff[jj] = arr * (128 * SG) + row * SG + ch * 4;
    }
    uint32_t sbase = (uint32_t)__cvta_generic_to_shared(sm);

    float acc[4][4][4];
    #pragma unroll
    for (int i = 0; i < 4; i++)
        #pragma unroll
        for (int j = 0; j < 4; j++)
            #pragma unroll
            for (int c = 0; c < 4; c++) acc[i][j][c] = 0.f;

    const int nk = K >> 5;

    #pragma unroll
    for (int jj = 0; jj < 4; jj++)
        cpa16(sbase + dstoff[jj] * 4, src[jj]);
    CP_COMMIT;

    for (int kc = 0; kc < nk; kc++) {
        int cur = kc & 1;
        if (kc + 1 < nk) {
            uint32_t bb = sbase + (cur ^ 1) * TBUF_B;
            int kadv = (kc + 1) * 16;
            #pragma unroll
            for (int jj = 0; jj < 4; jj++)
                cpa16(bb + dstoff[jj] * 4, src[jj] + kadv);
            CP_COMMIT;
            CP_WAIT1;
        } else {
            CP_WAIT0;
        }
        __syncthreads();

        uint32_t bb = sbase + cur * TBUF_B;
        #pragma unroll
        for (int s = 0; s < 2; s++) {
            uint32_t aH[4][4];
            #pragma unroll
            for (int i = 0; i < 4; i++)
                ldm4(aH[i], bb + (aoff[i] + 8 * s) * 4);
            #pragma unroll
            for (int jj = 0; jj < 2; jj++) {
                uint32_t bh[4];
                ldm4(bh, bb + AREA_BH + (boff[jj] + 8 * s) * 4);
                #pragma unroll
                for (int i = 0; i < 4; i++) {
                    mma_f16(acc[i][2 * jj],     aH[i][0], aH[i][1], aH[i][2], aH[i][3], bh[0], bh[2]);
                    mma_f16(acc[i][2 * jj + 1], aH[i][0], aH[i][1], aH[i][2], aH[i][3], bh[1], bh[3]);
                }
            }
        }
        __syncthreads();
    }

    // ---- epilogue (undo x64 weight scaling) ----
    const float INV = 1.f / 64.f;
    #pragma unroll
    for (int i = 0; i < 4; i++) {
        int r0 = by * 128 + wm + 16 * i + tg;
        #pragma unroll
        for (int j = 0; j < 4; j++) {
            int col = bx * 128 + wn + 8 * j + 2 * t4;
            float2 v0 = make_float2(acc[i][j][0] * INV, acc[i][j][1] * INV);
            float2 v1 = make_float2(acc[i][j][2] * INV, acc[i][j][3] * INV);
            if (QKV) {
                if (col < DIM) {
                    rope_store_h(g_Qh, KP, r0, col, v0, cs, sn);
                    rope_store_h(g_Qh, KP, r0 + 8, col, v1, cs, sn);
                } else if (col < DIM + KVDIM) {
                    int c2 = col - DIM;
                    rope_store_h(g_Kh, KVP, r0, c2, v0, cs, sn);
                    rope_store_h(g_Kh, KVP, r0 + 8, c2, v1, cs, sn);
                } else {
                    int c2 = col - DIM - KVDIM;
                    vt_store(r0, c2, v0);
                    vt_store(r0 + 8, c2, v1);
                }
            } else {
                *(float2*)(Cout + (size_t)r0 * DIM + col) = v0;
                *(float2*)(Cout + (size_t)(r0 + 8) * DIM + col) = v1;
            }
        }
    }
}

// ---------------- causal flash attention (pure fp16 mma) ---------------------
// S = Qh@Kh; O += Ph@Vh. 2 staged arrays (KH,VH): smem = 36,864 B.
#define SAT   36
#define KVBUF (2 * 64 * SAT)

__global__ __launch_bounds__(256, 2) void attn_mma() {
    extern __shared__ uint32_t smu[];

    const int qt = (int)gridDim.x - 1 - (int)blockIdx.x;   // heavy tiles first
    const int h = blockIdx.y, b = blockIdx.z;
    const int kvh = h >> 2;
    const int tid = threadIdx.x;
    const int w = tid >> 5, lane = tid & 31;
    const int tg = lane >> 2, t4 = lane & 3;
    const int rA = w * 16 + tg, rB = rA + 8;
    const int rowAg = b * SEQ + qt * 128 + rA;
    const int rowBg = rowAg + 8;
    const int wrowmax = qt * 128 + w * 16 + 15;

    const int mrow = ((lane >> 3) & 1) * 8 + (lane & 7);
    const int mcol = (lane >> 4) * 4;
    int nfoff[4];
    #pragma unroll
    for (int jj = 0; jj < 4; jj++) nfoff[jj] = (16 * jj + mrow) * SAT + mcol;

    const int crow = tid >> 3, cch = tid & 7;
    const uint32_t* kbase = g_Kh + (size_t)(b * SEQ + crow) * KVP + kvh * 32 + cch * 4;
    const uint32_t* vbase = g_Vth + (size_t)((b * 8 + kvh) * HD + crow) * (SEQ / 2) + cch * 4;
    const uint32_t kdst = crow * SAT + cch * 4;
    const uint32_t vdst = (64 * SAT) + crow * SAT + cch * 4;
    uint32_t sbase = (uint32_t)__cvta_generic_to_shared(smu);

    uint32_t qH[4][4];
    {
        const uint32_t* QA = g_Qh + (size_t)rowAg * KP + h * 32;
        const uint32_t* QB = g_Qh + (size_t)rowBg * KP + h * 32;
        #pragma unroll
        for (int s = 0; s < 4; s++) {
            qH[s][0] = QA[8 * s + t4];     qH[s][1] = QB[8 * s + t4];
            qH[s][2] = QA[8 * s + t4 + 4]; qH[s][3] = QB[8 * s + t4 + 4];
        }
    }

    float oacc[8][4];
    #pragma unroll
    for (int j = 0; j < 8; j++)
        #pragma unroll
        for (int c = 0; c < 4; c++) oacc[j][c] = 0.f;
    float mA = -1e30f, mB = -1e30f, lA = 0.f, lB = 0.f;
    const float SCL = 0.18033688011112042f;   // 0.125 * log2(e)

    const int nkb = 2 * qt + 2;

    #pragma unroll
    for (int jj = 0; jj < 2; jj++) {
        cpa16(sbase + (kdst + jj * 32 * SAT) * 4, kbase + (size_t)jj * 32 * KVP);
        cpa16(sbase + (vdst + jj * 32 * SAT) * 4, vbase + (size_t)jj * 32 * (SEQ / 2));
    }
    CP_COMMIT;

    for (int kb = 0; kb < nkb; kb++) {
        int cur = kb & 1;
        if (kb + 1 < nkb) {
            uint32_t boff = sbase + (cur ^ 1) * (KVBUF * 4);
            const uint32_t* kb2 = kbase + (size_t)(kb + 1) * 64 * KVP;
            const uint32_t* vb2 = vbase + (size_t)(kb + 1) * 32;
            #pragma unroll
            for (int jj = 0; jj < 2; jj++) {
                cpa16(boff + (kdst + jj * 32 * SAT) * 4, kb2 + (size_t)jj * 32 * KVP);
                cpa16(boff + (vdst + jj * 32 * SAT) * 4, vb2 + (size_t)jj * 32 * (SEQ / 2));
            }
            CP_COMMIT;
            CP_WAIT1;
        } else {
            CP_WAIT0;
        }
        __syncthreads();

        if (kb * 64 <= wrowmax) {
            uint32_t kvb = sbase + cur * (KVBUF * 4);
            const uint32_t VHo = 64 * SAT * 4;

            // ---- S = Qh @ Kh ----
            float sacc[8][4];
            #pragma unroll
            for (int j = 0; j < 8; j++)
                #pragma unroll
                for (int c = 0; c < 4; c++) sacc[j][c] = 0.f;
            #pragma unroll
            for (int s = 0; s < 4; s++) {
                #pragma unroll
                for (int jj = 0; jj < 4; jj++) {
                    uint32_t kh[4];
                    ldm4(kh, kvb + (nfoff[jj] + 8 * s) * 4);
                    mma_f16(sacc[2 * jj],     qH[s][0], qH[s][1], qH[s][2], qH[s][3], kh[0], kh[2]);
                    mma_f16(sacc[2 * jj + 1], qH[s][0], qH[s][1], qH[s][2], qH[s][3], kh[1], kh[3]);
                }
            }
            // causal mask on raw scores (diagonal tiles)
            if (kb >= 2 * qt) {
                int rGA = qt * 128 + rA, rGB = rGA + 8;
                #pragma unroll
                for (int j = 0; j < 8; j++) {
                    int c0 = kb * 64 + 8 * j + 2 * t4;
                    if (c0 > rGA)     sacc[j][0] = -1e30f;
                    if (c0 + 1 > rGA) sacc[j][1] = -1e30f;
                    if (c0 > rGB)     sacc[j][2] = -1e30f;
                    if (c0 + 1 > rGB) sacc[j][3] = -1e30f;
                }
            }

            // ---- online softmax ----
            float mxA = -1e30f, mxB = -1e30f;
            #pragma unroll
            for (int j = 0; j < 8; j++) {
                mxA = fmaxf(mxA, fmaxf(sacc[j][0], sacc[j][1]));
                mxB = fmaxf(mxB, fmaxf(sacc[j][2], sacc[j][3]));
            }
            mxA = fmaxf(mxA, __shfl_xor_sync(0xffffffffu, mxA, 1));
            mxA = fmaxf(mxA, __shfl_xor_sync(0xffffffffu, mxA, 2));
            mxB = fmaxf(mxB, __shfl_xor_sync(0xffffffffu, mxB, 1));
            mxB = fmaxf(mxB, __shfl_xor_sync(0xffffffffu, mxB, 2));
            float nmA = fmaxf(mA, mxA * SCL), nmB = fmaxf(mB, mxB * SCL);
            float aA = ex2(mA - nmA), aB = ex2(mB - nmB);
            mA = nmA; mB = nmB;
            float sumA = 0.f, sumB = 0.f;
            uint32_t ph01[8], ph23[8];
            #pragma unroll
            for (int j = 0; j < 8; j++) {
                float p0 = ex2(fmaf(sacc[j][0], SCL, -nmA));
                float p1 = ex2(fmaf(sacc[j][1], SCL, -nmA));
                float p2 = ex2(fmaf(sacc[j][2], SCL, -nmB));
                float p3 = ex2(fmaf(sacc[j][3], SCL, -nmB));
                sumA += p0 + p1; sumB += p2 + p3;
                ph01[j] = pack_h(p0, p1);
                ph23[j] = pack_h(p2, p3);
            }
            lA = lA * aA + sumA;
            lB = lB * aB + sumB;
            #pragma unroll
            for (int j = 0; j < 8; j++) {
                oacc[j][0] *= aA; oacc[j][1] *= aA;
                oacc[j][2] *= aB; oacc[j][3] *= aB;
            }

            // ---- O += Ph @ Vh ----
            #pragma unroll
            for (int s = 0; s < 4; s++) {
                uint32_t aH0 = ph01[2 * s],     aH1 = ph23[2 * s];
                uint32_t aH2 = ph01[2 * s + 1], aH3 = ph23[2 * s + 1];
                #pragma unroll
                for (int jj = 0; jj < 4; jj++) {
                    uint32_t vh[4];
                    ldm4(vh, kvb + VHo + (nfoff[jj] + 8 * s) * 4);
                    mma_f16(oacc[2 * jj],     aH0, aH1, aH2, aH3, vh[0], vh[2]);
                    mma_f16(oacc[2 * jj + 1], aH0, aH1, aH2, aH3, vh[1], vh[3]);
                }
            }
        }
        __syncthreads();
    }

    // final cross-thread l reduction
    lA += __shfl_xor_sync(0xffffffffu, lA, 1);
    lA += __shfl_xor_sync(0xffffffffu, lA, 2);
    lB += __shfl_xor_sync(0xffffffffu, lB, 1);
    lB += __shfl_xor_sync(0xffffffffu, lB, 2);

    float ilA = 1.f / lA, ilB = 1.f / lB;
    #pragma unroll
    for (int j = 0; j < 8; j++) {
        size_t oA = (size_t)rowAg * KP + h * 32 + 4 * j + t4;
        size_t oB = (size_t)rowBg * KP + h * 32 + 4 * j + t4;
        g_Ah[oA] = pack_h(oacc[j][0] * ilA, oacc[j][1] * ilA);
        g_Ah[oB] = pack_h(oacc[j][2] * ilB, oacc[j][3] * ilB);
    }
}

// ---------------- launch ----------------------------------------------------
extern "C" void kernel_launch(void* const* d_in, const int* in_sizes, int n_in,
                              void* d_out, int out_size) {
    const float* x  = (const float*)d_in[0];
    const float* fc = (const float*)d_in[1];
    const float* fs = (const float*)d_in[2];
    const float* wq = (const float*)d_in[3];
    const float* wk = (const float*)d_in[4];
    const float* wv = (const float*)d_in[5];
    const float* wo = (const float*)d_in[6];
    float* out = (float*)d_out;

    void *pxh, *pwh, *pwoh, *pAh;
    cudaGetSymbolAddress(&pxh, g_xh);
    cudaGetSymbolAddress(&pwh, g_wTh);
    cudaGetSymbolAddress(&pwoh, g_woTh);
    cudaGetSymbolAddress(&pAh, g_Ah);

    // ---- one-shot conversions ----
    conv_x<<<(ROWS * KP + 255) / 256, 256>>>(x, (uint32_t*)pxh, ROWS * KP);
    tconv_all<<<dim3(160, DIM / 64), 256>>>(wq, wk, wv, wo,
                                            (uint32_t*)pwh, (uint32_t*)pwoh);

    size_t gsmem = 2 * TBUF_B;   // 40960 B
    cudaFuncSetAttribute(gemm_f16<true>,  cudaFuncAttributeMaxDynamicSharedMemorySize, (int)gsmem);
    cudaFuncSetAttribute(gemm_f16<false>, cudaFuncAttributeMaxDynamicSharedMemorySize, (int)gsmem);

    // ---- fused QKV projection (epilogue: 1/64 + rope + V^T fp16) ----
    gemm_f16<true><<<dim3(NW / 128, ROWS / 128), 256, gsmem>>>(
        (uint32_t*)pxh, (uint32_t*)pwh, nullptr, fc, fs, DIM);

    // ---- attention ----
    {
        size_t smem = 2 * KVBUF * sizeof(uint32_t);  // 36864 B
        cudaFuncSetAttribute(attn_mma, cudaFuncAttributeMaxDynamicSharedMemorySize, (int)smem);
        attn_mma<<<dim3(SEQ / 128, N_HEADS, BSZ), 256, smem>>>();
    }

    // ---- output projection ----
    gemm_f16<false><<<dim3(DIM / 128, ROWS / 128), 256, gsmem>>>(
        (uint32_t*)pAh, (uint32_t*)pwoh, out, nullptr, nullptr, DIM);
}